// round 1
// baseline (speedup 1.0000x reference)
#include <cuda_runtime.h>
#include <math.h>

// Problem constants
#define B_   32
#define N_   1024
#define E_   16384
#define D_   128
#define M_   (B_*N_)      // 32768
#define KB_  256          // K_BUILD
#define H_   8
#define HD_  16
#define EPSF 1e-6f

// Output layout (flattened tuple: state_policy, state_value, node_mask, stage)
#define OFF_SV (M_*D_)            // 4194304
#define OFF_MK (OFF_SV + B_*258)  // 4202560
#define OFF_ST (OFF_MK + M_)      // 4235328

// ---------------- scratch (static device globals; no allocation) -------------
__device__ float g_h   [M_*D_];
__device__ float g_t   [M_*D_];
__device__ float g_fh  [M_*D_];
__device__ float g_acc [M_*D_];
__device__ float g_deg [M_];
__device__ float g_ga  [M_*D_];
__device__ float g_up  [M_*D_];
__device__ float g_h1  [M_*D_];
__device__ float g_h2  [M_*D_];
__device__ float g_q2  [M_*D_];
__device__ float g_k2  [B_*KB_*D_];
__device__ float g_v2  [B_*KB_*D_];
__device__ float g_oh  [M_*D_];
__device__ float g_hnum [B_*128];
__device__ float g_hmean[B_*128];
__device__ float g_Wf  [3*256*128];   // fused Wq,Wk,Wv
__device__ float g_bf  [3*128];       // fused biases
__device__ float g_zero[128];         // zero bias (zero-initialized)

// ---------------- generic fp32 GEMM: C[M,128] = epi(A@W + bias) --------------
// A is a virtual concat [A1 | A2] along K. A2 optionally divided by (deg+eps).
// Optional rowmap: global row m -> physical row (m/mapMod)*N_ + rowmap[m%mapMod]
// epi: 0 = none, 1 = tanh, 2 = tanh then + pos_enc[(row % N_)*128 + col]
__global__ void __launch_bounds__(256, 2) gemm_k(
    const float* __restrict__ A1, int lda1,
    const float* __restrict__ A2,
    const float* __restrict__ deg,
    const int*   __restrict__ rowmap, int mapMod,
    const float* __restrict__ W, int ldw, int wOff,
    const float* __restrict__ bias, int bOff,
    float* __restrict__ C,
    int K1, int K,
    int epi, const float* __restrict__ pos)
{
    __shared__ float As[16][128];
    __shared__ float Bs[16][128];
    const int tid = threadIdx.x;
    const int m0  = blockIdx.x * 128;
    const int ty  = tid >> 4;   // 0..15
    const int tx  = tid & 15;   // 0..15

    float acc[8][8];
    #pragma unroll
    for (int i = 0; i < 8; i++)
        #pragma unroll
        for (int j = 0; j < 8; j++) acc[i][j] = 0.f;

    for (int k0 = 0; k0 < K; k0 += 16) {
        // --- load A tile: 128 rows x 16 cols ---
        #pragma unroll
        for (int i = 0; i < 2; i++) {
            int idx = tid + i * 256;
            int mr  = idx >> 2;          // 0..127
            int c4  = (idx & 3) * 4;     // 0,4,8,12
            int gm  = m0 + mr;
            int pr  = gm;
            if (rowmap) pr = (gm / mapMod) * N_ + rowmap[gm % mapMod];
            int k = k0 + c4;
            float4 v;
            if (k < K1) {
                v = *(const float4*)&A1[(long)pr * lda1 + k];
            } else {
                v = *(const float4*)&A2[(long)pr * 128 + (k - K1)];
                if (deg) {
                    float s = 1.0f / (deg[pr] + EPSF);
                    v.x *= s; v.y *= s; v.z *= s; v.w *= s;
                }
            }
            As[c4 + 0][mr] = v.x; As[c4 + 1][mr] = v.y;
            As[c4 + 2][mr] = v.z; As[c4 + 3][mr] = v.w;
        }
        // --- load B tile: 16 rows x 128 cols ---
        #pragma unroll
        for (int i = 0; i < 2; i++) {
            int idx = tid + i * 256;
            int kr  = idx >> 5;          // 0..15
            int c4  = (idx & 31) * 4;
            float4 v = *(const float4*)&W[(long)(k0 + kr) * ldw + wOff + c4];
            *(float4*)&Bs[kr][c4] = v;
        }
        __syncthreads();
        #pragma unroll
        for (int kk = 0; kk < 16; kk++) {
            float a[8], b[8];
            #pragma unroll
            for (int i = 0; i < 8; i++) a[i] = As[kk][ty * 8 + i];
            #pragma unroll
            for (int j = 0; j < 8; j++) b[j] = Bs[kk][tx * 8 + j];
            #pragma unroll
            for (int i = 0; i < 8; i++)
                #pragma unroll
                for (int j = 0; j < 8; j++)
                    acc[i][j] += a[i] * b[j];
        }
        __syncthreads();
    }
    // --- epilogue ---
    #pragma unroll
    for (int i = 0; i < 8; i++) {
        int gm = m0 + ty * 8 + i;
        #pragma unroll
        for (int j = 0; j < 8; j++) {
            int col = tx * 8 + j;
            float v = acc[i][j] + bias[bOff + col];
            if (epi >= 1) v = tanhf(v);
            if (epi == 2) v += pos[(gm % N_) * 128 + col];
            C[(long)gm * 128 + col] = v;
        }
    }
}

// ---------------- fused attention projection biases ---------------------------
__global__ void fused_bias_k(const float* __restrict__ bq,
                             const float* __restrict__ bk,
                             const float* __restrict__ bv,
                             const float* __restrict__ Win,
                             const float* __restrict__ b_in,
                             float* __restrict__ bf)
{
    int s = blockIdx.x;        // 0,1,2
    int n = threadIdx.x;       // 0..127
    const float* bs = (s == 0) ? bq : (s == 1) ? bk : bv;
    float acc = b_in[s * 128 + n];
    for (int k = 0; k < 128; k++)
        acc += bs[k] * Win[k * 384 + s * 128 + n];
    bf[s * 128 + n] = acc;
}

// ---------------- h_num: two tiny tanh MLP layers in one block ---------------
__global__ void __launch_bounds__(256) hnum_k(
    const float* __restrict__ num,
    const float* __restrict__ W0, const float* __restrict__ b0,
    const float* __restrict__ W1, const float* __restrict__ b1,
    float* __restrict__ out)
{
    __shared__ float sn[32 * 64];
    __shared__ float sh[32 * 256];
    int tid = threadIdx.x;
    for (int i = tid; i < 32 * 64; i += 256) sn[i] = num[i];
    __syncthreads();
    for (int i = tid; i < 32 * 256; i += 256) {
        int r = i >> 8, c = i & 255;
        float a = b0[c];
        for (int k = 0; k < 64; k++) a += sn[r * 64 + k] * W0[k * 256 + c];
        sh[i] = tanhf(a);
    }
    __syncthreads();
    for (int i = tid; i < 32 * 128; i += 256) {
        int r = i >> 7, c = i & 127;
        float a = b1[c];
        for (int k = 0; k < 256; k++) a += sh[r * 256 + k] * W1[k * 128 + c];
        out[i] = tanhf(a);
    }
}

// ---------------- zero / scatter / combine -----------------------------------
__global__ void zero_k(float* __restrict__ p, int n)
{
    int i = (blockIdx.x * 256 + threadIdx.x) * 4;
    if (i < n) *(float4*)&p[i] = make_float4(0.f, 0.f, 0.f, 0.f);
}

// One warp per edge: acc[e0] += fh[e1]; acc[e1] += fh[e0]; deg[e0]++, deg[e1]++
__global__ void __launch_bounds__(256) scatter_k(
    const int* __restrict__ eidx,
    const float* __restrict__ fh,
    float* __restrict__ acc,
    float* __restrict__ deg)
{
    int g    = blockIdx.x * 8 + (threadIdx.x >> 5);   // edge id in [0, B*E)
    int lane = threadIdx.x & 31;
    int b    = g / E_;
    int base = b * N_;
    int e0 = eidx[2 * g];
    int e1 = eidx[2 * g + 1];
    int d  = lane * 4;
    float4 v1 = *(const float4*)&fh[(long)(base + e1) * D_ + d];
    float* p0 = &acc[(long)(base + e0) * D_ + d];
    atomicAdd(p0 + 0, v1.x); atomicAdd(p0 + 1, v1.y);
    atomicAdd(p0 + 2, v1.z); atomicAdd(p0 + 3, v1.w);
    float4 v0 = *(const float4*)&fh[(long)(base + e0) * D_ + d];
    float* p1 = &acc[(long)(base + e1) * D_ + d];
    atomicAdd(p1 + 0, v0.x); atomicAdd(p1 + 1, v0.y);
    atomicAdd(p1 + 2, v0.z); atomicAdd(p1 + 3, v0.w);
    if (lane == 0) {
        atomicAdd(&deg[base + e0], 1.0f);
        atomicAdd(&deg[base + e1], 1.0f);
    }
}

__global__ void combine_k(const float* __restrict__ g,
                          const float* __restrict__ u,
                          const float* __restrict__ h,
                          float* __restrict__ o, int n)
{
    int i = (blockIdx.x * 256 + threadIdx.x) * 4;
    if (i >= n) return;
    float4 G = *(const float4*)&g[i];
    float4 U = *(const float4*)&u[i];
    float4 Hh = *(const float4*)&h[i];
    float4 R;
    R.x = G.x * U.x + (1.f - G.x) * Hh.x;
    R.y = G.y * U.y + (1.f - G.y) * Hh.y;
    R.z = G.z * U.z + (1.f - G.z) * Hh.z;
    R.w = G.w * U.w + (1.f - G.w) * Hh.w;
    *(float4*)&o[i] = R;
}

// ---------------- attention: hd=16, 256 keys, softmax in smem ----------------
// 256 threads: thread pair (row r, half) splits the 256 keys in two.
#define KVSTRIDE 36      // per-jj row: [half0 16 | half1 16 | 4 pad] floats
#define SROW2    129
#define ATTN_SMEM ((128*KVSTRIDE*2 + 256*SROW2) * 4)

__global__ void __launch_bounds__(256) attn_k(
    const float* __restrict__ q2,
    const float* __restrict__ k2,
    const float* __restrict__ v2,
    float* __restrict__ oh)
{
    extern __shared__ float sm[];
    float* Ks = sm;
    float* Vs = sm + 128 * KVSTRIDE;
    float* S  = sm + 2 * 128 * KVSTRIDE;

    int qt = blockIdx.x, h = blockIdx.y, b = blockIdx.z;
    int tid = threadIdx.x;

    // load K/V for (b, h): 256 keys x 16 dims, staggered layout (bank-safe)
    for (int idx = tid; idx < 256 * 4; idx += 256) {
        int j  = idx >> 2;
        int d4 = (idx & 3) * 4;
        int dst = (j & 127) * KVSTRIDE + (j >> 7) * 16 + d4;
        *(float4*)&Ks[dst] = *(const float4*)&k2[(long)(b * KB_ + j) * D_ + h * HD_ + d4];
        *(float4*)&Vs[dst] = *(const float4*)&v2[(long)(b * KB_ + j) * D_ + h * HD_ + d4];
    }
    __syncthreads();

    int r    = tid >> 1;
    int half = tid & 1;
    int qi   = qt * 128 + r;
    const float* qp = &q2[(long)(b * N_ + qi) * D_ + h * HD_];
    float q[16];
    #pragma unroll
    for (int d = 0; d < 16; d += 4) {
        float4 v = *(const float4*)&qp[d];
        q[d] = v.x; q[d + 1] = v.y; q[d + 2] = v.z; q[d + 3] = v.w;
    }

    float* Srow = &S[tid * SROW2];
    float mx = -1e30f;
    for (int jj = 0; jj < 128; jj++) {
        int base = jj * KVSTRIDE + half * 16;
        float s = 0.f;
        #pragma unroll
        for (int d4 = 0; d4 < 16; d4 += 4) {
            float4 kv = *(const float4*)&Ks[base + d4];
            s += q[d4] * kv.x + q[d4 + 1] * kv.y + q[d4 + 2] * kv.z + q[d4 + 3] * kv.w;
        }
        s *= 0.25f;            // 1/sqrt(16)
        Srow[jj] = s;
        mx = fmaxf(mx, s);
    }
    mx = fmaxf(mx, __shfl_xor_sync(0xffffffffu, mx, 1));
    float sum = 0.f;
    for (int jj = 0; jj < 128; jj++) {
        float p = __expf(Srow[jj] - mx);
        Srow[jj] = p;
        sum += p;
    }
    sum += __shfl_xor_sync(0xffffffffu, sum, 1);
    float inv = 1.f / sum;

    float o[16];
    #pragma unroll
    for (int d = 0; d < 16; d++) o[d] = 0.f;
    for (int jj = 0; jj < 128; jj++) {
        float p = Srow[jj];
        int base = jj * KVSTRIDE + half * 16;
        #pragma unroll
        for (int d4 = 0; d4 < 16; d4 += 4) {
            float4 vv = *(const float4*)&Vs[base + d4];
            o[d4] += p * vv.x; o[d4 + 1] += p * vv.y;
            o[d4 + 2] += p * vv.z; o[d4 + 3] += p * vv.w;
        }
    }
    #pragma unroll
    for (int d = 0; d < 16; d++) o[d] += __shfl_xor_sync(0xffffffffu, o[d], 1);
    if (half == 0) {
        float* op = &oh[(long)(b * N_ + qi) * D_ + h * HD_];
        #pragma unroll
        for (int d = 0; d < 16; d += 4) {
            float4 v = make_float4(o[d] * inv, o[d + 1] * inv, o[d + 2] * inv, o[d + 3] * inv);
            *(float4*)&op[d] = v;
        }
    }
}

// ---------------- mean over N + tail writer ----------------------------------
__global__ void mean_k(const float* __restrict__ att, float* __restrict__ hmean)
{
    int b = blockIdx.x;       // 32
    int c = threadIdx.x;      // 128
    float s = 0.f;
    for (int n = 0; n < N_; n++)
        s += att[(long)(b * N_ + n) * D_ + c];
    hmean[b * D_ + c] = s * (1.0f / N_);
}

__global__ void tail_k(const float* __restrict__ hnum,
                       const float* __restrict__ hmean,
                       const float* __restrict__ stage,
                       float* __restrict__ out)
{
    int i = blockIdx.x * 256 + threadIdx.x;
    if (i < B_ * 258) {
        int b = i / 258, c = i % 258;
        float v = (c < 128) ? hnum[b * 128 + c]
                : (c < 256) ? hmean[b * 128 + (c - 128)]
                            : stage[b * 2 + (c - 256)];
        out[OFF_SV + i] = v;
    }
    if (i < M_) out[OFF_MK + i] = 1.0f;
    if (i < B_ * 2) out[OFF_ST + i] = stage[i];
}

// ---------------- launcher ----------------------------------------------------
extern "C" void kernel_launch(void* const* d_in, const int* in_sizes, int n_in,
                              void* d_out, int out_size)
{
    const float* numerical   = (const float*)d_in[0];
    const float* node_feat   = (const float*)d_in[1];
    const float* stage       = (const float*)d_in[2];
    const float* W_num0      = (const float*)d_in[3];
    const float* b_num0      = (const float*)d_in[4];
    const float* W_num1      = (const float*)d_in[5];
    const float* b_num1      = (const float*)d_in[6];
    const float* W_node      = (const float*)d_in[7];
    const float* b_node      = (const float*)d_in[8];
    const float* pos_enc     = (const float*)d_in[9];
    const float* ew1         = (const float*)d_in[10];
    const float* eb1         = (const float*)d_in[11];
    const float* ew2         = (const float*)d_in[12];
    const float* eb2         = (const float*)d_in[13];
    const float* Wg          = (const float*)d_in[14];
    const float* bg          = (const float*)d_in[15];
    const float* Wu          = (const float*)d_in[16];
    const float* bu          = (const float*)d_in[17];
    const float* Wq1         = (const float*)d_in[18];
    const float* bq1         = (const float*)d_in[19];
    const float* Wk1         = (const float*)d_in[20];
    const float* bk1         = (const float*)d_in[21];
    const float* Wv1         = (const float*)d_in[22];
    const float* bv1         = (const float*)d_in[23];
    const float* Win         = (const float*)d_in[24];
    const float* b_in        = (const float*)d_in[25];
    const float* Wout        = (const float*)d_in[26];
    const float* b_out       = (const float*)d_in[27];
    const int*   ei_dis      = (const int*)d_in[28];
    const int*   ei_od       = (const int*)d_in[29];
    const int*   build_idx   = (const int*)d_in[31];
    float* out = (float*)d_out;

    float *p_h, *p_t, *p_fh, *p_acc, *p_deg, *p_ga, *p_up, *p_h1, *p_h2;
    float *p_q2, *p_k2, *p_v2, *p_oh, *p_hnum, *p_hmean, *p_Wf, *p_bf, *p_zero;
    cudaGetSymbolAddress((void**)&p_h,    g_h);
    cudaGetSymbolAddress((void**)&p_t,    g_t);
    cudaGetSymbolAddress((void**)&p_fh,   g_fh);
    cudaGetSymbolAddress((void**)&p_acc,  g_acc);
    cudaGetSymbolAddress((void**)&p_deg,  g_deg);
    cudaGetSymbolAddress((void**)&p_ga,   g_ga);
    cudaGetSymbolAddress((void**)&p_up,   g_up);
    cudaGetSymbolAddress((void**)&p_h1,   g_h1);
    cudaGetSymbolAddress((void**)&p_h2,   g_h2);
    cudaGetSymbolAddress((void**)&p_q2,   g_q2);
    cudaGetSymbolAddress((void**)&p_k2,   g_k2);
    cudaGetSymbolAddress((void**)&p_v2,   g_v2);
    cudaGetSymbolAddress((void**)&p_oh,   g_oh);
    cudaGetSymbolAddress((void**)&p_hnum, g_hnum);
    cudaGetSymbolAddress((void**)&p_hmean,g_hmean);
    cudaGetSymbolAddress((void**)&p_Wf,   g_Wf);
    cudaGetSymbolAddress((void**)&p_bf,   g_bf);
    cudaGetSymbolAddress((void**)&p_zero, g_zero);

    // --- fused attention projection weights: Wf = W{q,k,v}1 @ Win slice ---
    gemm_k<<<2, 256>>>(Wq1, 128, nullptr, nullptr, nullptr, 0,
                       Win, 384, 0,   p_zero, 0, p_Wf,          128, 128, 0, nullptr);
    gemm_k<<<2, 256>>>(Wk1, 128, nullptr, nullptr, nullptr, 0,
                       Win, 384, 128, p_zero, 0, p_Wf + 32768,  128, 128, 0, nullptr);
    gemm_k<<<2, 256>>>(Wv1, 128, nullptr, nullptr, nullptr, 0,
                       Win, 384, 256, p_zero, 0, p_Wf + 65536,  128, 128, 0, nullptr);
    fused_bias_k<<<3, 128>>>(bq1, bk1, bv1, Win, b_in, p_bf);

    // --- h_num MLP ---
    hnum_k<<<1, 256>>>(numerical, W_num0, b_num0, W_num1, b_num1, p_hnum);

    // --- h = tanh(node_feature @ W_node + b_node) + pos_enc ---
    gemm_k<<<256, 256>>>(node_feat, 32, nullptr, nullptr, nullptr, 0,
                         W_node, 128, 0, b_node, 0, p_h, 32, 32, 2, pos_enc);

    // --- two message-passing branches (only last GCN layer matters) ---
    for (int L = 0; L < 2; L++) {
        const float* ew = L ? ew2 : ew1;
        const float* eb = L ? eb2 : eb1;
        const int*   ei = L ? ei_od : ei_dis;
        float* hout = L ? p_h2 : p_h1;
        // edge MLP applied to nodes (gather commutes with rowwise MLP)
        gemm_k<<<256, 256>>>(p_h, 128, nullptr, nullptr, nullptr, 0,
                             ew + 32768, 128, 0, eb, 256, p_t, 128, 128, 1, nullptr);
        gemm_k<<<256, 256>>>(p_t, 128, nullptr, nullptr, nullptr, 0,
                             ew + 49152, 128, 0, eb, 384, p_fh, 128, 128, 1, nullptr);
        zero_k<<<M_*D_/1024, 256>>>(p_acc, M_*D_);
        zero_k<<<M_/1024,    256>>>(p_deg, M_);
        scatter_k<<<B_*E_/8, 256>>>(ei, p_fh, p_acc, p_deg);
        // gate/update GEMMs on [h | h_comb] (h_comb = acc/(deg+eps) in loader)
        gemm_k<<<256, 256>>>(p_h, 128, p_acc, p_deg, nullptr, 0,
                             Wg, 128, 0, bg, 0, p_ga, 128, 256, 1, nullptr);
        gemm_k<<<256, 256>>>(p_h, 128, p_acc, p_deg, nullptr, 0,
                             Wu, 128, 0, bu, 0, p_up, 128, 256, 1, nullptr);
        combine_k<<<M_*D_/1024, 256>>>(p_ga, p_up, p_h, hout, M_*D_);
    }

    // --- q2 / k2 / v2 projections with fused weights ---
    gemm_k<<<256, 256>>>(p_h1, 128, p_h2, nullptr, nullptr, 0,
                         p_Wf, 128, 0, p_bf, 0, p_q2, 128, 256, 0, nullptr);
    gemm_k<<<64, 256>>>(p_h1, 128, p_h2, nullptr, build_idx, 256,
                        p_Wf + 32768, 128, 0, p_bf, 128, p_k2, 128, 256, 0, nullptr);
    gemm_k<<<64, 256>>>(p_h1, 128, p_h2, nullptr, build_idx, 256,
                        p_Wf + 65536, 128, 0, p_bf, 256, p_v2, 128, 256, 0, nullptr);

    // --- attention ---
    cudaFuncSetAttribute(attn_k, cudaFuncAttributeMaxDynamicSharedMemorySize, ATTN_SMEM);
    attn_k<<<dim3(8, H_, B_), 256, ATTN_SMEM>>>(p_q2, p_k2, p_v2, p_oh);

    // --- h_att = oh @ W_out + b_out  -> state_policy region of d_out ---
    gemm_k<<<256, 256>>>(p_oh, 128, nullptr, nullptr, nullptr, 0,
                         Wout, 128, 0, b_out, 0, out, 128, 128, 0, nullptr);

    // --- mean + tail outputs ---
    mean_k<<<B_, 128>>>(out, p_hmean);
    tail_k<<<129, 256>>>(p_hnum, p_hmean, stage, out);

    (void)in_sizes; (void)n_in; (void)out_size;
}

// round 2
// speedup vs baseline: 1.0369x; 1.0369x over previous
#include <cuda_runtime.h>
#include <math.h>

// Problem constants
#define B_   32
#define N_   1024
#define E_   16384
#define D_   128
#define M_   (B_*N_)      // 32768
#define KB_  256          // K_BUILD
#define H_   8
#define HD_  16
#define EPSF 1e-6f

// Output layout (flattened tuple: state_policy, state_value, node_mask, stage)
#define OFF_SV (M_*D_)            // 4194304
#define OFF_MK (OFF_SV + B_*258)  // 4202560
#define OFF_ST (OFF_MK + M_)      // 4235328

// ---------------- scratch (static device globals; no allocation) -------------
__device__ float g_h   [M_*D_];
__device__ float g_t   [M_*D_];
__device__ float g_fh  [M_*D_];
__device__ float g_acc [M_*D_];
__device__ float g_deg [M_];
__device__ float g_ga  [M_*D_];
__device__ float g_up  [M_*D_];
__device__ float g_h1  [M_*D_];
__device__ float g_h2  [M_*D_];
__device__ float g_q2  [M_*D_];
__device__ float g_k2  [B_*KB_*D_];
__device__ float g_v2  [B_*KB_*D_];
__device__ float g_oh  [M_*D_];
__device__ float g_hnum [B_*128];
__device__ float g_hmean[B_*128];
__device__ float g_part [B_*8*128];
__device__ float g_Wf  [3*256*128];   // fused Wq,Wk,Wv
__device__ float g_bf  [3*128];       // fused biases
__device__ float g_zero[128];         // zero bias (zero-initialized)
__device__ float g_A   [(long)B_*N_*N_];   // batched adjacency counts (134MB)

// ---------------- generic fp32 GEMM: C[M,128] = epi(A@W + bias) --------------
__global__ void __launch_bounds__(256, 2) gemm_k(
    const float* __restrict__ A1, int lda1,
    const float* __restrict__ A2,
    const float* __restrict__ deg,
    const int*   __restrict__ rowmap, int mapMod,
    const float* __restrict__ W, int ldw, int wOff,
    const float* __restrict__ bias, int bOff,
    float* __restrict__ C,
    int K1, int K,
    int epi, const float* __restrict__ pos)
{
    __shared__ float As[16][128];
    __shared__ float Bs[16][128];
    const int tid = threadIdx.x;
    const int m0  = blockIdx.x * 128;
    const int ty  = tid >> 4;   // 0..15
    const int tx  = tid & 15;   // 0..15

    float acc[8][8];
    #pragma unroll
    for (int i = 0; i < 8; i++)
        #pragma unroll
        for (int j = 0; j < 8; j++) acc[i][j] = 0.f;

    for (int k0 = 0; k0 < K; k0 += 16) {
        #pragma unroll
        for (int i = 0; i < 2; i++) {
            int idx = tid + i * 256;
            int mr  = idx >> 2;
            int c4  = (idx & 3) * 4;
            int gm  = m0 + mr;
            int pr  = gm;
            if (rowmap) pr = (gm / mapMod) * N_ + rowmap[gm % mapMod];
            int k = k0 + c4;
            float4 v;
            if (k < K1) {
                v = *(const float4*)&A1[(long)pr * lda1 + k];
            } else {
                v = *(const float4*)&A2[(long)pr * 128 + (k - K1)];
                if (deg) {
                    float s = 1.0f / (deg[pr] + EPSF);
                    v.x *= s; v.y *= s; v.z *= s; v.w *= s;
                }
            }
            As[c4 + 0][mr] = v.x; As[c4 + 1][mr] = v.y;
            As[c4 + 2][mr] = v.z; As[c4 + 3][mr] = v.w;
        }
        #pragma unroll
        for (int i = 0; i < 2; i++) {
            int idx = tid + i * 256;
            int kr  = idx >> 5;
            int c4  = (idx & 31) * 4;
            float4 v = *(const float4*)&W[(long)(k0 + kr) * ldw + wOff + c4];
            *(float4*)&Bs[kr][c4] = v;
        }
        __syncthreads();
        #pragma unroll
        for (int kk = 0; kk < 16; kk++) {
            float a[8], b[8];
            #pragma unroll
            for (int i = 0; i < 8; i++) a[i] = As[kk][ty * 8 + i];
            #pragma unroll
            for (int j = 0; j < 8; j++) b[j] = Bs[kk][tx * 8 + j];
            #pragma unroll
            for (int i = 0; i < 8; i++)
                #pragma unroll
                for (int j = 0; j < 8; j++)
                    acc[i][j] += a[i] * b[j];
        }
        __syncthreads();
    }
    #pragma unroll
    for (int i = 0; i < 8; i++) {
        int gm = m0 + ty * 8 + i;
        #pragma unroll
        for (int j = 0; j < 8; j++) {
            int col = tx * 8 + j;
            float v = acc[i][j] + bias[bOff + col];
            if (epi >= 1) v = tanhf(v);
            if (epi == 2) v += pos[(gm % N_) * 128 + col];
            C[(long)gm * 128 + col] = v;
        }
    }
}

// ---- batched adjacency aggregation: acc[b] = A[b] @ fh[b], deg = rowsum(A) --
__global__ void __launch_bounds__(256, 2) adj_gemm_k(
    const float* __restrict__ A,
    const float* __restrict__ fh,
    float* __restrict__ acc,
    float* __restrict__ deg)
{
    __shared__ float As[16][128];
    __shared__ float Bs[16][128];
    const int tid = threadIdx.x;
    const int b   = blockIdx.y;
    const int m0  = blockIdx.x * 128;
    const int ty  = tid >> 4;
    const int tx  = tid & 15;
    const float* Ab  = A  + (long)b * N_ * N_;
    const float* fhb = fh + (long)b * N_ * D_;

    float c[8][8];
    float dsum[8];
    #pragma unroll
    for (int i = 0; i < 8; i++) {
        dsum[i] = 0.f;
        #pragma unroll
        for (int j = 0; j < 8; j++) c[i][j] = 0.f;
    }

    for (int k0 = 0; k0 < N_; k0 += 16) {
        #pragma unroll
        for (int i = 0; i < 2; i++) {
            int idx = tid + i * 256;
            int mr  = idx >> 2;
            int c4  = (idx & 3) * 4;
            float4 v = *(const float4*)&Ab[(long)(m0 + mr) * N_ + k0 + c4];
            As[c4 + 0][mr] = v.x; As[c4 + 1][mr] = v.y;
            As[c4 + 2][mr] = v.z; As[c4 + 3][mr] = v.w;
        }
        #pragma unroll
        for (int i = 0; i < 2; i++) {
            int idx = tid + i * 256;
            int kr  = idx >> 5;
            int c4  = (idx & 31) * 4;
            *(float4*)&Bs[kr][c4] = *(const float4*)&fhb[(long)(k0 + kr) * D_ + c4];
        }
        __syncthreads();
        #pragma unroll
        for (int kk = 0; kk < 16; kk++) {
            float a[8], bb[8];
            #pragma unroll
            for (int i = 0; i < 8; i++) a[i] = As[kk][ty * 8 + i];
            #pragma unroll
            for (int j = 0; j < 8; j++) bb[j] = Bs[kk][tx * 8 + j];
            #pragma unroll
            for (int i = 0; i < 8; i++) {
                dsum[i] += a[i];
                #pragma unroll
                for (int j = 0; j < 8; j++)
                    c[i][j] += a[i] * bb[j];
            }
        }
        __syncthreads();
    }
    #pragma unroll
    for (int i = 0; i < 8; i++) {
        int gm = b * N_ + m0 + ty * 8 + i;
        #pragma unroll
        for (int j = 0; j < 8; j++)
            acc[(long)gm * 128 + tx * 8 + j] = c[i][j];
        if (tx == 0) deg[gm] = dsum[i];
    }
}

// ---- build adjacency: A[b][e0][e1] += 1; A[b][e1][e0] += 1 ------------------
__global__ void __launch_bounds__(256) edgebuild_k(
    const int* __restrict__ eidx, float* __restrict__ A)
{
    int g = blockIdx.x * 256 + threadIdx.x;       // edge id in [0, B*E)
    int b = g / E_;
    long base = (long)b * N_ * N_;
    int e0 = eidx[2 * g];
    int e1 = eidx[2 * g + 1];
    atomicAdd(&A[base + (long)e0 * N_ + e1], 1.0f);
    atomicAdd(&A[base + (long)e1 * N_ + e0], 1.0f);
}

// ---------------- fused attention projection biases ---------------------------
__global__ void fused_bias_k(const float* __restrict__ bq,
                             const float* __restrict__ bk,
                             const float* __restrict__ bv,
                             const float* __restrict__ Win,
                             const float* __restrict__ b_in,
                             float* __restrict__ bf)
{
    int s = blockIdx.x;
    int n = threadIdx.x;
    const float* bs = (s == 0) ? bq : (s == 1) ? bk : bv;
    float acc = b_in[s * 128 + n];
    for (int k = 0; k < 128; k++)
        acc += bs[k] * Win[k * 384 + s * 128 + n];
    bf[s * 128 + n] = acc;
}

// ---------------- h_num MLP ---------------------------------------------------
__global__ void __launch_bounds__(256) hnum_k(
    const float* __restrict__ num,
    const float* __restrict__ W0, const float* __restrict__ b0,
    const float* __restrict__ W1, const float* __restrict__ b1,
    float* __restrict__ out)
{
    __shared__ float sn[32 * 64];
    __shared__ float sh[32 * 256];
    int tid = threadIdx.x;
    for (int i = tid; i < 32 * 64; i += 256) sn[i] = num[i];
    __syncthreads();
    for (int i = tid; i < 32 * 256; i += 256) {
        int r = i >> 8, c = i & 255;
        float a = b0[c];
        for (int k = 0; k < 64; k++) a += sn[r * 64 + k] * W0[k * 256 + c];
        sh[i] = tanhf(a);
    }
    __syncthreads();
    for (int i = tid; i < 32 * 128; i += 256) {
        int r = i >> 7, c = i & 127;
        float a = b1[c];
        for (int k = 0; k < 256; k++) a += sh[r * 256 + k] * W1[k * 128 + c];
        out[i] = tanhf(a);
    }
}

// ---------------- zero / combine ----------------------------------------------
__global__ void zero_k(float* __restrict__ p, long n)
{
    long i = ((long)blockIdx.x * 256 + threadIdx.x) * 4;
    if (i < n) *(float4*)&p[i] = make_float4(0.f, 0.f, 0.f, 0.f);
}

__global__ void combine_k(const float* __restrict__ g,
                          const float* __restrict__ u,
                          const float* __restrict__ h,
                          float* __restrict__ o, int n)
{
    int i = (blockIdx.x * 256 + threadIdx.x) * 4;
    if (i >= n) return;
    float4 G = *(const float4*)&g[i];
    float4 U = *(const float4*)&u[i];
    float4 Hh = *(const float4*)&h[i];
    float4 R;
    R.x = G.x * U.x + (1.f - G.x) * Hh.x;
    R.y = G.y * U.y + (1.f - G.y) * Hh.y;
    R.z = G.z * U.z + (1.f - G.z) * Hh.z;
    R.w = G.w * U.w + (1.f - G.w) * Hh.w;
    *(float4*)&o[i] = R;
}

// ---------------- attention: hd=16, 256 keys, softmax in smem ----------------
#define KVSTRIDE 36
#define SROW2    129
#define ATTN_SMEM ((128*KVSTRIDE*2 + 256*SROW2) * 4)

__global__ void __launch_bounds__(256) attn_k(
    const float* __restrict__ q2,
    const float* __restrict__ k2,
    const float* __restrict__ v2,
    float* __restrict__ oh)
{
    extern __shared__ float sm[];
    float* Ks = sm;
    float* Vs = sm + 128 * KVSTRIDE;
    float* S  = sm + 2 * 128 * KVSTRIDE;

    int qt = blockIdx.x, h = blockIdx.y, b = blockIdx.z;
    int tid = threadIdx.x;

    for (int idx = tid; idx < 256 * 4; idx += 256) {
        int j  = idx >> 2;
        int d4 = (idx & 3) * 4;
        int dst = (j & 127) * KVSTRIDE + (j >> 7) * 16 + d4;
        *(float4*)&Ks[dst] = *(const float4*)&k2[(long)(b * KB_ + j) * D_ + h * HD_ + d4];
        *(float4*)&Vs[dst] = *(const float4*)&v2[(long)(b * KB_ + j) * D_ + h * HD_ + d4];
    }
    __syncthreads();

    int r    = tid >> 1;
    int half = tid & 1;
    int qi   = qt * 128 + r;
    const float* qp = &q2[(long)(b * N_ + qi) * D_ + h * HD_];
    float q[16];
    #pragma unroll
    for (int d = 0; d < 16; d += 4) {
        float4 v = *(const float4*)&qp[d];
        q[d] = v.x; q[d + 1] = v.y; q[d + 2] = v.z; q[d + 3] = v.w;
    }

    float* Srow = &S[tid * SROW2];
    float mx = -1e30f;
    for (int jj = 0; jj < 128; jj++) {
        int base = jj * KVSTRIDE + half * 16;
        float s = 0.f;
        #pragma unroll
        for (int d4 = 0; d4 < 16; d4 += 4) {
            float4 kv = *(const float4*)&Ks[base + d4];
            s += q[d4] * kv.x + q[d4 + 1] * kv.y + q[d4 + 2] * kv.z + q[d4 + 3] * kv.w;
        }
        s *= 0.25f;
        Srow[jj] = s;
        mx = fmaxf(mx, s);
    }
    mx = fmaxf(mx, __shfl_xor_sync(0xffffffffu, mx, 1));
    float sum = 0.f;
    for (int jj = 0; jj < 128; jj++) {
        float p = __expf(Srow[jj] - mx);
        Srow[jj] = p;
        sum += p;
    }
    sum += __shfl_xor_sync(0xffffffffu, sum, 1);
    float inv = 1.f / sum;

    float o[16];
    #pragma unroll
    for (int d = 0; d < 16; d++) o[d] = 0.f;
    for (int jj = 0; jj < 128; jj++) {
        float p = Srow[jj];
        int base = jj * KVSTRIDE + half * 16;
        #pragma unroll
        for (int d4 = 0; d4 < 16; d4 += 4) {
            float4 vv = *(const float4*)&Vs[base + d4];
            o[d4] += p * vv.x; o[d4 + 1] += p * vv.y;
            o[d4 + 2] += p * vv.z; o[d4 + 3] += p * vv.w;
        }
    }
    #pragma unroll
    for (int d = 0; d < 16; d++) o[d] += __shfl_xor_sync(0xffffffffu, o[d], 1);
    if (half == 0) {
        float* op = &oh[(long)(b * N_ + qi) * D_ + h * HD_];
        #pragma unroll
        for (int d = 0; d < 16; d += 4) {
            float4 v = make_float4(o[d] * inv, o[d + 1] * inv, o[d + 2] * inv, o[d + 3] * inv);
            *(float4*)&op[d] = v;
        }
    }
}

// ---------------- two-phase deterministic mean over N -------------------------
__global__ void mean1_k(const float* __restrict__ att, float* __restrict__ part)
{
    int b = blockIdx.x, ch = blockIdx.y, c = threadIdx.x;
    float s = 0.f;
    int n0 = ch * 128;
    for (int n = n0; n < n0 + 128; n++)
        s += att[(long)(b * N_ + n) * D_ + c];
    part[(b * 8 + ch) * 128 + c] = s;
}

__global__ void mean2_k(const float* __restrict__ part, float* __restrict__ hmean)
{
    int b = blockIdx.x, c = threadIdx.x;
    float s = 0.f;
    #pragma unroll
    for (int ch = 0; ch < 8; ch++)
        s += part[(b * 8 + ch) * 128 + c];
    hmean[b * 128 + c] = s * (1.0f / N_);
}

__global__ void tail_k(const float* __restrict__ hnum,
                       const float* __restrict__ hmean,
                       const float* __restrict__ stage,
                       float* __restrict__ out)
{
    int i = blockIdx.x * 256 + threadIdx.x;
    if (i < B_ * 258) {
        int b = i / 258, c = i % 258;
        float v = (c < 128) ? hnum[b * 128 + c]
                : (c < 256) ? hmean[b * 128 + (c - 128)]
                            : stage[b * 2 + (c - 256)];
        out[OFF_SV + i] = v;
    }
    if (i < M_) out[OFF_MK + i] = 1.0f;
    if (i < B_ * 2) out[OFF_ST + i] = stage[i];
}

// ---------------- launcher ----------------------------------------------------
extern "C" void kernel_launch(void* const* d_in, const int* in_sizes, int n_in,
                              void* d_out, int out_size)
{
    const float* numerical   = (const float*)d_in[0];
    const float* node_feat   = (const float*)d_in[1];
    const float* stage       = (const float*)d_in[2];
    const float* W_num0      = (const float*)d_in[3];
    const float* b_num0      = (const float*)d_in[4];
    const float* W_num1      = (const float*)d_in[5];
    const float* b_num1      = (const float*)d_in[6];
    const float* W_node      = (const float*)d_in[7];
    const float* b_node      = (const float*)d_in[8];
    const float* pos_enc     = (const float*)d_in[9];
    const float* ew1         = (const float*)d_in[10];
    const float* eb1         = (const float*)d_in[11];
    const float* ew2         = (const float*)d_in[12];
    const float* eb2         = (const float*)d_in[13];
    const float* Wg          = (const float*)d_in[14];
    const float* bg          = (const float*)d_in[15];
    const float* Wu          = (const float*)d_in[16];
    const float* bu          = (const float*)d_in[17];
    const float* Wq1         = (const float*)d_in[18];
    const float* bq1         = (const float*)d_in[19];
    const float* Wk1         = (const float*)d_in[20];
    const float* bk1         = (const float*)d_in[21];
    const float* Wv1         = (const float*)d_in[22];
    const float* bv1         = (const float*)d_in[23];
    const float* Win         = (const float*)d_in[24];
    const float* b_in        = (const float*)d_in[25];
    const float* Wout        = (const float*)d_in[26];
    const float* b_out       = (const float*)d_in[27];
    const int*   ei_dis      = (const int*)d_in[28];
    const int*   ei_od       = (const int*)d_in[29];
    const int*   build_idx   = (const int*)d_in[31];
    float* out = (float*)d_out;

    float *p_h, *p_t, *p_fh, *p_acc, *p_deg, *p_ga, *p_up, *p_h1, *p_h2;
    float *p_q2, *p_k2, *p_v2, *p_oh, *p_hnum, *p_hmean, *p_part, *p_Wf, *p_bf, *p_zero, *p_A;
    cudaGetSymbolAddress((void**)&p_h,    g_h);
    cudaGetSymbolAddress((void**)&p_t,    g_t);
    cudaGetSymbolAddress((void**)&p_fh,   g_fh);
    cudaGetSymbolAddress((void**)&p_acc,  g_acc);
    cudaGetSymbolAddress((void**)&p_deg,  g_deg);
    cudaGetSymbolAddress((void**)&p_ga,   g_ga);
    cudaGetSymbolAddress((void**)&p_up,   g_up);
    cudaGetSymbolAddress((void**)&p_h1,   g_h1);
    cudaGetSymbolAddress((void**)&p_h2,   g_h2);
    cudaGetSymbolAddress((void**)&p_q2,   g_q2);
    cudaGetSymbolAddress((void**)&p_k2,   g_k2);
    cudaGetSymbolAddress((void**)&p_v2,   g_v2);
    cudaGetSymbolAddress((void**)&p_oh,   g_oh);
    cudaGetSymbolAddress((void**)&p_hnum, g_hnum);
    cudaGetSymbolAddress((void**)&p_hmean,g_hmean);
    cudaGetSymbolAddress((void**)&p_part, g_part);
    cudaGetSymbolAddress((void**)&p_Wf,   g_Wf);
    cudaGetSymbolAddress((void**)&p_bf,   g_bf);
    cudaGetSymbolAddress((void**)&p_zero, g_zero);
    cudaGetSymbolAddress((void**)&p_A,    g_A);

    // --- fused attention projection weights ---
    gemm_k<<<2, 256>>>(Wq1, 128, nullptr, nullptr, nullptr, 0,
                       Win, 384, 0,   p_zero, 0, p_Wf,          128, 128, 0, nullptr);
    gemm_k<<<2, 256>>>(Wk1, 128, nullptr, nullptr, nullptr, 0,
                       Win, 384, 128, p_zero, 0, p_Wf + 32768,  128, 128, 0, nullptr);
    gemm_k<<<2, 256>>>(Wv1, 128, nullptr, nullptr, nullptr, 0,
                       Win, 384, 256, p_zero, 0, p_Wf + 65536,  128, 128, 0, nullptr);
    fused_bias_k<<<3, 128>>>(bq1, bk1, bv1, Win, b_in, p_bf);

    hnum_k<<<1, 256>>>(numerical, W_num0, b_num0, W_num1, b_num1, p_hnum);

    // --- h = tanh(node_feature @ W_node + b_node) + pos_enc ---
    gemm_k<<<256, 256>>>(node_feat, 32, nullptr, nullptr, nullptr, 0,
                         W_node, 128, 0, b_node, 0, p_h, 32, 32, 2, pos_enc);

    // --- two message-passing branches ---
    for (int L = 0; L < 2; L++) {
        const float* ew = L ? ew2 : ew1;
        const float* eb = L ? eb2 : eb1;
        const int*   ei = L ? ei_od : ei_dis;
        float* hout = L ? p_h2 : p_h1;
        gemm_k<<<256, 256>>>(p_h, 128, nullptr, nullptr, nullptr, 0,
                             ew + 32768, 128, 0, eb, 256, p_t, 128, 128, 1, nullptr);
        gemm_k<<<256, 256>>>(p_t, 128, nullptr, nullptr, nullptr, 0,
                             ew + 49152, 128, 0, eb, 384, p_fh, 128, 128, 1, nullptr);
        // adjacency-count GEMM formulation of the segment-sum
        zero_k<<<(int)(((long)B_*N_*N_)/1024), 256>>>(p_A, (long)B_*N_*N_);
        edgebuild_k<<<B_*E_/256, 256>>>(ei, p_A);
        adj_gemm_k<<<dim3(8, 32), 256>>>(p_A, p_fh, p_acc, p_deg);
        gemm_k<<<256, 256>>>(p_h, 128, p_acc, p_deg, nullptr, 0,
                             Wg, 128, 0, bg, 0, p_ga, 128, 256, 1, nullptr);
        gemm_k<<<256, 256>>>(p_h, 128, p_acc, p_deg, nullptr, 0,
                             Wu, 128, 0, bu, 0, p_up, 128, 256, 1, nullptr);
        combine_k<<<M_*D_/1024, 256>>>(p_ga, p_up, p_h, hout, M_*D_);
    }

    // --- q2 / k2 / v2 projections with fused weights ---
    gemm_k<<<256, 256>>>(p_h1, 128, p_h2, nullptr, nullptr, 0,
                         p_Wf, 128, 0, p_bf, 0, p_q2, 128, 256, 0, nullptr);
    gemm_k<<<64, 256>>>(p_h1, 128, p_h2, nullptr, build_idx, 256,
                        p_Wf + 32768, 128, 0, p_bf, 128, p_k2, 128, 256, 0, nullptr);
    gemm_k<<<64, 256>>>(p_h1, 128, p_h2, nullptr, build_idx, 256,
                        p_Wf + 65536, 128, 0, p_bf, 256, p_v2, 128, 256, 0, nullptr);

    // --- attention ---
    cudaFuncSetAttribute(attn_k, cudaFuncAttributeMaxDynamicSharedMemorySize, ATTN_SMEM);
    attn_k<<<dim3(8, H_, B_), 256, ATTN_SMEM>>>(p_q2, p_k2, p_v2, p_oh);

    // --- h_att = oh @ W_out + b_out ---
    gemm_k<<<256, 256>>>(p_oh, 128, nullptr, nullptr, nullptr, 0,
                         Wout, 128, 0, b_out, 0, out, 128, 128, 0, nullptr);

    // --- mean + tail ---
    mean1_k<<<dim3(32, 8), 128>>>(out, p_part);
    mean2_k<<<32, 128>>>(p_part, p_hmean);
    tail_k<<<129, 256>>>(p_hnum, p_hmean, stage, out);

    (void)in_sizes; (void)n_in; (void)out_size;
}

// round 5
// speedup vs baseline: 1.4110x; 1.3608x over previous
#include <cuda_runtime.h>
#include <math.h>
#include <stdint.h>

// Problem constants
#define B_   32
#define N_   1024
#define E_   16384
#define D_   128
#define M_   (B_*N_)      // 32768
#define KB_  256
#define H_   8
#define HD_  16
#define EPSF 1e-6f

#define OFF_SV (M_*D_)
#define OFF_MK (OFF_SV + B_*258)
#define OFF_ST (OFF_MK + M_)

// ---------------- scratch ----------------
__device__ float g_h   [M_*D_];
__device__ float g_t   [M_*D_];
__device__ float g_fh  [M_*D_];
__device__ float g_acc [M_*D_];
__device__ float g_deg [M_];
__device__ float g_ga  [M_*D_];
__device__ float g_up  [M_*D_];
__device__ float g_h1  [M_*D_];
__device__ float g_h2  [M_*D_];
__device__ float g_q2  [M_*D_];
__device__ float g_k2  [B_*KB_*D_];
__device__ float g_v2  [B_*KB_*D_];
__device__ float g_oh  [M_*D_];
__device__ float g_hnum [B_*128];
__device__ float g_hmean[B_*128];
__device__ float g_part [B_*8*128];
__device__ float g_Wf  [3*256*128];
__device__ float g_bf  [3*128];
__device__ float g_zero[128];
__device__ float g_A   [(long)B_*N_*N_];   // batched adjacency counts (134MB)

// ---------------- helpers ----------------
__device__ __forceinline__ float to_tf32(float x) {
    uint32_t u;
    asm("cvt.rna.tf32.f32 %0, %1;" : "=r"(u) : "f"(x));
    return __uint_as_float(u);
}

__device__ __forceinline__ void mma_tf32(float c[4], const uint32_t a[4], const uint32_t b[2]) {
    asm volatile(
        "mma.sync.aligned.m16n8k8.row.col.f32.tf32.tf32.f32 "
        "{%0,%1,%2,%3}, {%4,%5,%6,%7}, {%8,%9}, {%0,%1,%2,%3};"
        : "+f"(c[0]), "+f"(c[1]), "+f"(c[2]), "+f"(c[3])
        : "r"(a[0]), "r"(a[1]), "r"(a[2]), "r"(a[3]), "r"(b[0]), "r"(b[1]));
}

// fast exp on FMA pipe: exp(x) = 2^n * P(f), t = x*log2e = n + f, f in [-0.5,0.5]
// P(f) ~= 2^f (Taylor in f). rel err ~2e-6.
__device__ __forceinline__ float fexp(float x) {
    x = fmaxf(x, -87.0f);
    float t = x * 1.4426950408889634f;
    float fn = rintf(t);
    float f = t - fn;
    float p = 1.3333558146e-3f;
    p = fmaf(p, f, 9.6179662376e-3f);
    p = fmaf(p, f, 5.5490420128e-2f);
    p = fmaf(p, f, 2.4022650696e-1f);
    p = fmaf(p, f, 6.9314718056e-1f);
    p = fmaf(p, f, 1.0f);
    int n = (int)fn;
    float sc = __int_as_float((n + 127) << 23);
    return p * sc;
}

// ------- split-tf32 tensor-core GEMM (near-fp32): C = epi(A@W + bias) --------
// A virtual concat [A1(lda1) | A2(128, /(deg+eps))]. epi: 0 none, 1 tanh.
__global__ void __launch_bounds__(256, 2) tgemm3_k(
    const float* __restrict__ A1, int lda1,
    const float* __restrict__ A2,
    const float* __restrict__ deg,
    const float* __restrict__ W, int ldw, int wOff,
    const float* __restrict__ bias, int bOff,
    float* __restrict__ C,
    int K1, int K, int epi)
{
    __shared__ float AsH[16][136];
    __shared__ float AsL[16][136];
    __shared__ float BsH[16][136];
    __shared__ float BsL[16][136];
    const int tid  = threadIdx.x;
    const int m0   = blockIdx.x * 128;
    const int warp = tid >> 5;
    const int lane = tid & 31;
    const int m0w  = (warp >> 2) * 64;
    const int n0w  = (warp & 3) * 32;
    const int g    = lane >> 2;
    const int tig  = lane & 3;

    float c[4][4][4];
    #pragma unroll
    for (int mf = 0; mf < 4; mf++)
        #pragma unroll
        for (int nf = 0; nf < 4; nf++)
            #pragma unroll
            for (int q = 0; q < 4; q++) c[mf][nf][q] = 0.f;

    for (int k0 = 0; k0 < K; k0 += 16) {
        #pragma unroll
        for (int i = 0; i < 2; i++) {
            int idx = tid + i * 256;
            int mr  = idx >> 2;
            int c4  = (idx & 3) * 4;
            int pr  = m0 + mr;
            int k   = k0 + c4;
            float4 v;
            if (k < K1) {
                v = *(const float4*)&A1[(long)pr * lda1 + k];
            } else {
                v = *(const float4*)&A2[(long)pr * 128 + (k - K1)];
                if (deg) {
                    float s = 1.0f / (deg[pr] + EPSF);
                    v.x *= s; v.y *= s; v.z *= s; v.w *= s;
                }
            }
            float hx = to_tf32(v.x), hy = to_tf32(v.y), hz = to_tf32(v.z), hw = to_tf32(v.w);
            AsH[c4 + 0][mr] = hx; AsL[c4 + 0][mr] = to_tf32(v.x - hx);
            AsH[c4 + 1][mr] = hy; AsL[c4 + 1][mr] = to_tf32(v.y - hy);
            AsH[c4 + 2][mr] = hz; AsL[c4 + 2][mr] = to_tf32(v.z - hz);
            AsH[c4 + 3][mr] = hw; AsL[c4 + 3][mr] = to_tf32(v.w - hw);
        }
        #pragma unroll
        for (int i = 0; i < 2; i++) {
            int idx = tid + i * 256;
            int kr  = idx >> 5;
            int c4  = (idx & 31) * 4;
            float4 v = *(const float4*)&W[(long)(k0 + kr) * ldw + wOff + c4];
            float hx = to_tf32(v.x), hy = to_tf32(v.y), hz = to_tf32(v.z), hw = to_tf32(v.w);
            BsH[kr][c4 + 0] = hx; BsL[kr][c4 + 0] = to_tf32(v.x - hx);
            BsH[kr][c4 + 1] = hy; BsL[kr][c4 + 1] = to_tf32(v.y - hy);
            BsH[kr][c4 + 2] = hz; BsL[kr][c4 + 2] = to_tf32(v.z - hz);
            BsH[kr][c4 + 3] = hw; BsL[kr][c4 + 3] = to_tf32(v.w - hw);
        }
        __syncthreads();
        #pragma unroll
        for (int kk = 0; kk < 2; kk++) {
            int kb = kk * 8;
            uint32_t bh[4][2], bl[4][2];
            #pragma unroll
            for (int nf = 0; nf < 4; nf++) {
                int nc = n0w + nf * 8 + g;
                bh[nf][0] = __float_as_uint(BsH[kb + tig    ][nc]);
                bh[nf][1] = __float_as_uint(BsH[kb + tig + 4][nc]);
                bl[nf][0] = __float_as_uint(BsL[kb + tig    ][nc]);
                bl[nf][1] = __float_as_uint(BsL[kb + tig + 4][nc]);
            }
            #pragma unroll
            for (int mf = 0; mf < 4; mf++) {
                int mcol = m0w + mf * 16 + g;
                uint32_t ah[4], al[4];
                ah[0] = __float_as_uint(AsH[kb + tig    ][mcol]);
                ah[1] = __float_as_uint(AsH[kb + tig    ][mcol + 8]);
                ah[2] = __float_as_uint(AsH[kb + tig + 4][mcol]);
                ah[3] = __float_as_uint(AsH[kb + tig + 4][mcol + 8]);
                al[0] = __float_as_uint(AsL[kb + tig    ][mcol]);
                al[1] = __float_as_uint(AsL[kb + tig    ][mcol + 8]);
                al[2] = __float_as_uint(AsL[kb + tig + 4][mcol]);
                al[3] = __float_as_uint(AsL[kb + tig + 4][mcol + 8]);
                #pragma unroll
                for (int nf = 0; nf < 4; nf++) {
                    mma_tf32(c[mf][nf], al, bh[nf]);
                    mma_tf32(c[mf][nf], ah, bl[nf]);
                    mma_tf32(c[mf][nf], ah, bh[nf]);
                }
            }
        }
        __syncthreads();
    }
    #pragma unroll
    for (int mf = 0; mf < 4; mf++) {
        int row0 = m0 + m0w + mf * 16 + g;
        #pragma unroll
        for (int nf = 0; nf < 4; nf++) {
            int col = n0w + nf * 8 + 2 * tig;
            float b0 = bias[bOff + col], b1 = bias[bOff + col + 1];
            float v00 = c[mf][nf][0] + b0, v01 = c[mf][nf][1] + b1;
            float v10 = c[mf][nf][2] + b0, v11 = c[mf][nf][3] + b1;
            if (epi == 1) { v00 = tanhf(v00); v01 = tanhf(v01); v10 = tanhf(v10); v11 = tanhf(v11); }
            *(float2*)&C[(long)row0 * 128 + col]       = make_float2(v00, v01);
            *(float2*)&C[(long)(row0 + 8) * 128 + col] = make_float2(v10, v11);
        }
    }
}

// ---- adjacency aggregation: acc[b] = A[b] @ fh[b]; A exact in tf32 ----------
__global__ void __launch_bounds__(256, 2) adj_tgemm2_k(
    const float* __restrict__ A,
    const float* __restrict__ fh,
    float* __restrict__ acc)
{
    __shared__ float As [16][136];
    __shared__ float BsH[16][136];
    __shared__ float BsL[16][136];
    const int tid  = threadIdx.x;
    const int bb   = blockIdx.y;
    const int m0   = blockIdx.x * 128;
    const int warp = tid >> 5;
    const int lane = tid & 31;
    const int m0w  = (warp >> 2) * 64;
    const int n0w  = (warp & 3) * 32;
    const int g    = lane >> 2;
    const int tig  = lane & 3;
    const float* Ab  = A  + (long)bb * N_ * N_;
    const float* fhb = fh + (long)bb * N_ * D_;

    float c[4][4][4];
    #pragma unroll
    for (int mf = 0; mf < 4; mf++)
        #pragma unroll
        for (int nf = 0; nf < 4; nf++)
            #pragma unroll
            for (int q = 0; q < 4; q++) c[mf][nf][q] = 0.f;

    for (int k0 = 0; k0 < N_; k0 += 16) {
        #pragma unroll
        for (int i = 0; i < 2; i++) {
            int idx = tid + i * 256;
            int mr  = idx >> 2;
            int c4  = (idx & 3) * 4;
            float4 v = *(const float4*)&Ab[(long)(m0 + mr) * N_ + k0 + c4];
            As[c4 + 0][mr] = v.x; As[c4 + 1][mr] = v.y;
            As[c4 + 2][mr] = v.z; As[c4 + 3][mr] = v.w;
        }
        #pragma unroll
        for (int i = 0; i < 2; i++) {
            int idx = tid + i * 256;
            int kr  = idx >> 5;
            int c4  = (idx & 31) * 4;
            float4 v = *(const float4*)&fhb[(long)(k0 + kr) * D_ + c4];
            float hx = to_tf32(v.x), hy = to_tf32(v.y), hz = to_tf32(v.z), hw = to_tf32(v.w);
            BsH[kr][c4 + 0] = hx; BsL[kr][c4 + 0] = to_tf32(v.x - hx);
            BsH[kr][c4 + 1] = hy; BsL[kr][c4 + 1] = to_tf32(v.y - hy);
            BsH[kr][c4 + 2] = hz; BsL[kr][c4 + 2] = to_tf32(v.z - hz);
            BsH[kr][c4 + 3] = hw; BsL[kr][c4 + 3] = to_tf32(v.w - hw);
        }
        __syncthreads();
        #pragma unroll
        for (int kk = 0; kk < 2; kk++) {
            int kb = kk * 8;
            uint32_t bh[4][2], bl[4][2];
            #pragma unroll
            for (int nf = 0; nf < 4; nf++) {
                int nc = n0w + nf * 8 + g;
                bh[nf][0] = __float_as_uint(BsH[kb + tig    ][nc]);
                bh[nf][1] = __float_as_uint(BsH[kb + tig + 4][nc]);
                bl[nf][0] = __float_as_uint(BsL[kb + tig    ][nc]);
                bl[nf][1] = __float_as_uint(BsL[kb + tig + 4][nc]);
            }
            #pragma unroll
            for (int mf = 0; mf < 4; mf++) {
                int mcol = m0w + mf * 16 + g;
                uint32_t a[4];
                a[0] = __float_as_uint(As[kb + tig    ][mcol]);
                a[1] = __float_as_uint(As[kb + tig    ][mcol + 8]);
                a[2] = __float_as_uint(As[kb + tig + 4][mcol]);
                a[3] = __float_as_uint(As[kb + tig + 4][mcol + 8]);
                #pragma unroll
                for (int nf = 0; nf < 4; nf++) {
                    mma_tf32(c[mf][nf], a, bl[nf]);
                    mma_tf32(c[mf][nf], a, bh[nf]);
                }
            }
        }
        __syncthreads();
    }
    #pragma unroll
    for (int mf = 0; mf < 4; mf++) {
        int row0 = bb * N_ + m0 + m0w + mf * 16 + g;
        #pragma unroll
        for (int nf = 0; nf < 4; nf++) {
            int col = n0w + nf * 8 + 2 * tig;
            *(float2*)&acc[(long)row0 * 128 + col]       = make_float2(c[mf][nf][0], c[mf][nf][1]);
            *(float2*)&acc[(long)(row0 + 8) * 128 + col] = make_float2(c[mf][nf][2], c[mf][nf][3]);
        }
    }
}

// ---------------- scalar fp32 GEMM (small/irregular cases) -------------------
__global__ void __launch_bounds__(256, 2) gemm_k(
    const float* __restrict__ A1, int lda1,
    const float* __restrict__ A2,
    const float* __restrict__ deg,
    const int*   __restrict__ rowmap, int mapMod,
    const float* __restrict__ W, int ldw, int wOff,
    const float* __restrict__ bias, int bOff,
    float* __restrict__ C,
    int K1, int K,
    int epi, const float* __restrict__ pos)
{
    __shared__ float As[16][128];
    __shared__ float Bs[16][128];
    const int tid = threadIdx.x;
    const int m0  = blockIdx.x * 128;
    const int ty  = tid >> 4;
    const int tx  = tid & 15;

    float acc[8][8];
    #pragma unroll
    for (int i = 0; i < 8; i++)
        #pragma unroll
        for (int j = 0; j < 8; j++) acc[i][j] = 0.f;

    for (int k0 = 0; k0 < K; k0 += 16) {
        #pragma unroll
        for (int i = 0; i < 2; i++) {
            int idx = tid + i * 256;
            int mr  = idx >> 2;
            int c4  = (idx & 3) * 4;
            int gm  = m0 + mr;
            int pr  = gm;
            if (rowmap) pr = (gm / mapMod) * N_ + rowmap[gm % mapMod];
            int k = k0 + c4;
            float4 v;
            if (k < K1) {
                v = *(const float4*)&A1[(long)pr * lda1 + k];
            } else {
                v = *(const float4*)&A2[(long)pr * 128 + (k - K1)];
                if (deg) {
                    float s = 1.0f / (deg[pr] + EPSF);
                    v.x *= s; v.y *= s; v.z *= s; v.w *= s;
                }
            }
            As[c4 + 0][mr] = v.x; As[c4 + 1][mr] = v.y;
            As[c4 + 2][mr] = v.z; As[c4 + 3][mr] = v.w;
        }
        #pragma unroll
        for (int i = 0; i < 2; i++) {
            int idx = tid + i * 256;
            int kr  = idx >> 5;
            int c4  = (idx & 31) * 4;
            float4 v = *(const float4*)&W[(long)(k0 + kr) * ldw + wOff + c4];
            *(float4*)&Bs[kr][c4] = v;
        }
        __syncthreads();
        #pragma unroll
        for (int kk = 0; kk < 16; kk++) {
            float a[8], b[8];
            #pragma unroll
            for (int i = 0; i < 8; i++) a[i] = As[kk][ty * 8 + i];
            #pragma unroll
            for (int j = 0; j < 8; j++) b[j] = Bs[kk][tx * 8 + j];
            #pragma unroll
            for (int i = 0; i < 8; i++)
                #pragma unroll
                for (int j = 0; j < 8; j++)
                    acc[i][j] += a[i] * b[j];
        }
        __syncthreads();
    }
    #pragma unroll
    for (int i = 0; i < 8; i++) {
        int gm = m0 + ty * 8 + i;
        #pragma unroll
        for (int j = 0; j < 8; j++) {
            int col = tx * 8 + j;
            float v = acc[i][j] + bias[bOff + col];
            if (epi >= 1) v = tanhf(v);
            if (epi == 2) v += pos[(gm % N_) * 128 + col];
            C[(long)gm * 128 + col] = v;
        }
    }
}

// ---- build adjacency + degree ------------------------------------------------
__global__ void __launch_bounds__(256) edgebuild_k(
    const int* __restrict__ eidx, float* __restrict__ A, float* __restrict__ deg)
{
    int g = blockIdx.x * 256 + threadIdx.x;
    int b = g / E_;
    long base = (long)b * N_ * N_;
    int e0 = eidx[2 * g];
    int e1 = eidx[2 * g + 1];
    atomicAdd(&A[base + (long)e0 * N_ + e1], 1.0f);
    atomicAdd(&A[base + (long)e1 * N_ + e0], 1.0f);
    atomicAdd(&deg[b * N_ + e0], 1.0f);
    atomicAdd(&deg[b * N_ + e1], 1.0f);
}

// ---------------- small fused kernels ----------------------------------------
__global__ void fused_bias_k(const float* __restrict__ bq,
                             const float* __restrict__ bk,
                             const float* __restrict__ bv,
                             const float* __restrict__ Win,
                             const float* __restrict__ b_in,
                             float* __restrict__ bf)
{
    int s = blockIdx.x;
    int n = threadIdx.x;
    const float* bs = (s == 0) ? bq : (s == 1) ? bk : bv;
    float acc = b_in[s * 128 + n];
    for (int k = 0; k < 128; k++)
        acc += bs[k] * Win[k * 384 + s * 128 + n];
    bf[s * 128 + n] = acc;
}

__global__ void __launch_bounds__(256) hnum_k(
    const float* __restrict__ num,
    const float* __restrict__ W0, const float* __restrict__ b0,
    const float* __restrict__ W1, const float* __restrict__ b1,
    float* __restrict__ out)
{
    __shared__ float sn[32 * 64];
    __shared__ float sh[32 * 256];
    int tid = threadIdx.x;
    for (int i = tid; i < 32 * 64; i += 256) sn[i] = num[i];
    __syncthreads();
    for (int i = tid; i < 32 * 256; i += 256) {
        int r = i >> 8, c = i & 255;
        float a = b0[c];
        for (int k = 0; k < 64; k++) a += sn[r * 64 + k] * W0[k * 256 + c];
        sh[i] = tanhf(a);
    }
    __syncthreads();
    for (int i = tid; i < 32 * 128; i += 256) {
        int r = i >> 7, c = i & 127;
        float a = b1[c];
        for (int k = 0; k < 256; k++) a += sh[r * 256 + k] * W1[k * 128 + c];
        out[i] = tanhf(a);
    }
}

__global__ void zero_k(float* __restrict__ p, long n)
{
    long i = ((long)blockIdx.x * 256 + threadIdx.x) * 4;
    if (i < n) *(float4*)&p[i] = make_float4(0.f, 0.f, 0.f, 0.f);
}

__global__ void combine_k(const float* __restrict__ g,
                          const float* __restrict__ u,
                          const float* __restrict__ h,
                          float* __restrict__ o, int n)
{
    int i = (blockIdx.x * 256 + threadIdx.x) * 4;
    if (i >= n) return;
    float4 G = *(const float4*)&g[i];
    float4 U = *(const float4*)&u[i];
    float4 Hh = *(const float4*)&h[i];
    float4 R;
    R.x = G.x * U.x + (1.f - G.x) * Hh.x;
    R.y = G.y * U.y + (1.f - G.y) * Hh.y;
    R.z = G.z * U.z + (1.f - G.z) * Hh.z;
    R.w = G.w * U.w + (1.f - G.w) * Hh.w;
    *(float4*)&o[i] = R;
}

// ---------------- attention: 1 row/thread, broadcast K/V, poly exp -----------
__global__ void __launch_bounds__(256) attn2_k(
    const float* __restrict__ q2,
    const float* __restrict__ k2,
    const float* __restrict__ v2,
    float* __restrict__ oh)
{
    __shared__ float Ks[256][16];
    __shared__ float Vs[256][16];
    int qt = blockIdx.x, h = blockIdx.y, b = blockIdx.z;
    int tid = threadIdx.x;

    #pragma unroll
    for (int i = 0; i < 4; i++) {
        int idx = tid + i * 256;
        int j  = idx >> 2;
        int d4 = (idx & 3) * 4;
        *(float4*)&Ks[j][d4] = *(const float4*)&k2[(long)(b * KB_ + j) * D_ + h * HD_ + d4];
        *(float4*)&Vs[j][d4] = *(const float4*)&v2[(long)(b * KB_ + j) * D_ + h * HD_ + d4];
    }
    __syncthreads();

    int qi = qt * 256 + tid;
    const float* qp = &q2[(long)(b * N_ + qi) * D_ + h * HD_];
    float q[16];
    #pragma unroll
    for (int d = 0; d < 16; d += 4) {
        float4 v = *(const float4*)&qp[d];
        q[d] = v.x * 0.25f; q[d+1] = v.y * 0.25f; q[d+2] = v.z * 0.25f; q[d+3] = v.w * 0.25f;
    }

    float m = -1e30f, sum = 0.f;
    float o[16];
    #pragma unroll
    for (int d = 0; d < 16; d++) o[d] = 0.f;

    for (int jj = 0; jj < 256; jj++) {
        float s = 0.f;
        float kreg[16];
        #pragma unroll
        for (int d4 = 0; d4 < 16; d4 += 4) {
            float4 kv = *(const float4*)&Ks[jj][d4];
            kreg[d4] = kv.x; kreg[d4+1] = kv.y; kreg[d4+2] = kv.z; kreg[d4+3] = kv.w;
        }
        #pragma unroll
        for (int d = 0; d < 16; d++) s = fmaf(q[d], kreg[d], s);
        float p;
        if (s > m) {
            float c = fexp(m - s);
            sum *= c;
            #pragma unroll
            for (int d = 0; d < 16; d++) o[d] *= c;
            m = s;
            p = 1.0f;
        } else {
            p = fexp(s - m);
        }
        sum += p;
        #pragma unroll
        for (int d4 = 0; d4 < 16; d4 += 4) {
            float4 vv = *(const float4*)&Vs[jj][d4];
            o[d4]   = fmaf(p, vv.x, o[d4]);
            o[d4+1] = fmaf(p, vv.y, o[d4+1]);
            o[d4+2] = fmaf(p, vv.z, o[d4+2]);
            o[d4+3] = fmaf(p, vv.w, o[d4+3]);
        }
    }
    float inv = 1.0f / sum;
    float* op = &oh[(long)(b * N_ + qi) * D_ + h * HD_];
    #pragma unroll
    for (int d = 0; d < 16; d += 4)
        *(float4*)&op[d] = make_float4(o[d]*inv, o[d+1]*inv, o[d+2]*inv, o[d+3]*inv);
}

// ---------------- mean + tail -------------------------------------------------
__global__ void mean1_k(const float* __restrict__ att, float* __restrict__ part)
{
    int b = blockIdx.x, ch = blockIdx.y, c = threadIdx.x;
    float s = 0.f;
    int n0 = ch * 128;
    for (int n = n0; n < n0 + 128; n++)
        s += att[(long)(b * N_ + n) * D_ + c];
    part[(b * 8 + ch) * 128 + c] = s;
}

__global__ void mean2_k(const float* __restrict__ part, float* __restrict__ hmean)
{
    int b = blockIdx.x, c = threadIdx.x;
    float s = 0.f;
    #pragma unroll
    for (int ch = 0; ch < 8; ch++)
        s += part[(b * 8 + ch) * 128 + c];
    hmean[b * 128 + c] = s * (1.0f / N_);
}

__global__ void tail_k(const float* __restrict__ hnum,
                       const float* __restrict__ hmean,
                       const float* __restrict__ stage,
                       float* __restrict__ out)
{
    int i = blockIdx.x * 256 + threadIdx.x;
    if (i < B_ * 258) {
        int b = i / 258, c = i % 258;
        float v = (c < 128) ? hnum[b * 128 + c]
                : (c < 256) ? hmean[b * 128 + (c - 128)]
                            : stage[b * 2 + (c - 256)];
        out[OFF_SV + i] = v;
    }
    if (i < M_) out[OFF_MK + i] = 1.0f;
    if (i < B_ * 2) out[OFF_ST + i] = stage[i];
}

// ---------------- launcher ----------------------------------------------------
extern "C" void kernel_launch(void* const* d_in, const int* in_sizes, int n_in,
                              void* d_out, int out_size)
{
    const float* numerical   = (const float*)d_in[0];
    const float* node_feat   = (const float*)d_in[1];
    const float* stage       = (const float*)d_in[2];
    const float* W_num0      = (const float*)d_in[3];
    const float* b_num0      = (const float*)d_in[4];
    const float* W_num1      = (const float*)d_in[5];
    const float* b_num1      = (const float*)d_in[6];
    const float* W_node      = (const float*)d_in[7];
    const float* b_node      = (const float*)d_in[8];
    const float* pos_enc     = (const float*)d_in[9];
    const float* ew1         = (const float*)d_in[10];
    const float* eb1         = (const float*)d_in[11];
    const float* ew2         = (const float*)d_in[12];
    const float* eb2         = (const float*)d_in[13];
    const float* Wg          = (const float*)d_in[14];
    const float* bg          = (const float*)d_in[15];
    const float* Wu          = (const float*)d_in[16];
    const float* bu          = (const float*)d_in[17];
    const float* Wq1         = (const float*)d_in[18];
    const float* bq1         = (const float*)d_in[19];
    const float* Wk1         = (const float*)d_in[20];
    const float* bk1         = (const float*)d_in[21];
    const float* Wv1         = (const float*)d_in[22];
    const float* bv1         = (const float*)d_in[23];
    const float* Win         = (const float*)d_in[24];
    const float* b_in        = (const float*)d_in[25];
    const float* Wout        = (const float*)d_in[26];
    const float* b_out       = (const float*)d_in[27];
    const int*   ei_dis      = (const int*)d_in[28];
    const int*   ei_od       = (const int*)d_in[29];
    const int*   build_idx   = (const int*)d_in[31];
    float* out = (float*)d_out;

    float *p_h, *p_t, *p_fh, *p_acc, *p_deg, *p_ga, *p_up, *p_h1, *p_h2;
    float *p_q2, *p_k2, *p_v2, *p_oh, *p_hnum, *p_hmean, *p_part, *p_Wf, *p_bf, *p_zero, *p_A;
    cudaGetSymbolAddress((void**)&p_h,    g_h);
    cudaGetSymbolAddress((void**)&p_t,    g_t);
    cudaGetSymbolAddress((void**)&p_fh,   g_fh);
    cudaGetSymbolAddress((void**)&p_acc,  g_acc);
    cudaGetSymbolAddress((void**)&p_deg,  g_deg);
    cudaGetSymbolAddress((void**)&p_ga,   g_ga);
    cudaGetSymbolAddress((void**)&p_up,   g_up);
    cudaGetSymbolAddress((void**)&p_h1,   g_h1);
    cudaGetSymbolAddress((void**)&p_h2,   g_h2);
    cudaGetSymbolAddress((void**)&p_q2,   g_q2);
    cudaGetSymbolAddress((void**)&p_k2,   g_k2);
    cudaGetSymbolAddress((void**)&p_v2,   g_v2);
    cudaGetSymbolAddress((void**)&p_oh,   g_oh);
    cudaGetSymbolAddress((void**)&p_hnum, g_hnum);
    cudaGetSymbolAddress((void**)&p_hmean,g_hmean);
    cudaGetSymbolAddress((void**)&p_part, g_part);
    cudaGetSymbolAddress((void**)&p_Wf,   g_Wf);
    cudaGetSymbolAddress((void**)&p_bf,   g_bf);
    cudaGetSymbolAddress((void**)&p_zero, g_zero);
    cudaGetSymbolAddress((void**)&p_A,    g_A);

    // fused attention projection weights (tiny, exact fp32)
    gemm_k<<<2, 256>>>(Wq1, 128, nullptr, nullptr, nullptr, 0,
                       Win, 384, 0,   p_zero, 0, p_Wf,          128, 128, 0, nullptr);
    gemm_k<<<2, 256>>>(Wk1, 128, nullptr, nullptr, nullptr, 0,
                       Win, 384, 128, p_zero, 0, p_Wf + 32768,  128, 128, 0, nullptr);
    gemm_k<<<2, 256>>>(Wv1, 128, nullptr, nullptr, nullptr, 0,
                       Win, 384, 256, p_zero, 0, p_Wf + 65536,  128, 128, 0, nullptr);
    fused_bias_k<<<3, 128>>>(bq1, bk1, bv1, Win, b_in, p_bf);

    hnum_k<<<1, 256>>>(numerical, W_num0, b_num0, W_num1, b_num1, p_hnum);

    // h = tanh(node_feature @ W_node + b_node) + pos_enc (fp32 root)
    gemm_k<<<256, 256>>>(node_feat, 32, nullptr, nullptr, nullptr, 0,
                         W_node, 128, 0, b_node, 0, p_h, 32, 32, 2, pos_enc);

    // two message-passing branches (last GCN layer only)
    for (int L = 0; L < 2; L++) {
        const float* ew = L ? ew2 : ew1;
        const float* eb = L ? eb2 : eb1;
        const int*   ei = L ? ei_od : ei_dis;
        float* hout = L ? p_h2 : p_h1;
        tgemm3_k<<<256, 256>>>(p_h, 128, nullptr, nullptr,
                               ew + 32768, 128, 0, eb, 256, p_t, 128, 128, 1);
        tgemm3_k<<<256, 256>>>(p_t, 128, nullptr, nullptr,
                               ew + 49152, 128, 0, eb, 384, p_fh, 128, 128, 1);
        zero_k<<<(int)(((long)B_*N_*N_)/1024), 256>>>(p_A, (long)B_*N_*N_);
        zero_k<<<M_/1024, 256>>>(p_deg, M_);
        edgebuild_k<<<B_*E_/256, 256>>>(ei, p_A, p_deg);
        adj_tgemm2_k<<<dim3(8, 32), 256>>>(p_A, p_fh, p_acc);
        tgemm3_k<<<256, 256>>>(p_h, 128, p_acc, p_deg,
                               Wg, 128, 0, bg, 0, p_ga, 128, 256, 1);
        tgemm3_k<<<256, 256>>>(p_h, 128, p_acc, p_deg,
                               Wu, 128, 0, bu, 0, p_up, 128, 256, 1);
        combine_k<<<M_*D_/1024, 256>>>(p_ga, p_up, p_h, hout, M_*D_);
    }

    // q2 (split-tf32 TC), k2/v2 (small, scalar with gather)
    tgemm3_k<<<256, 256>>>(p_h1, 128, p_h2, nullptr,
                           p_Wf, 128, 0, p_bf, 0, p_q2, 128, 256, 0);
    gemm_k<<<64, 256>>>(p_h1, 128, p_h2, nullptr, build_idx, 256,
                        p_Wf + 32768, 128, 0, p_bf, 128, p_k2, 128, 256, 0, nullptr);
    gemm_k<<<64, 256>>>(p_h1, 128, p_h2, nullptr, build_idx, 256,
                        p_Wf + 65536, 128, 0, p_bf, 256, p_v2, 128, 256, 0, nullptr);

    // attention
    attn2_k<<<dim3(4, H_, B_), 256>>>(p_q2, p_k2, p_v2, p_oh);

    // h_att = oh @ W_out + b_out
    tgemm3_k<<<256, 256>>>(p_oh, 128, nullptr, nullptr,
                           Wout, 128, 0, b_out, 0, out, 128, 128, 0);

    // mean + tail
    mean1_k<<<dim3(32, 8), 128>>>(out, p_part);
    mean2_k<<<32, 128>>>(p_part, p_hmean);
    tail_k<<<129, 256>>>(p_hnum, p_hmean, stage, out);

    (void)in_sizes; (void)n_in; (void)out_size;
}

// round 8
// speedup vs baseline: 1.8974x; 1.3447x over previous
#include <cuda_runtime.h>
#include <math.h>
#include <stdint.h>

// Problem constants
#define B_   32
#define N_   1024
#define E_   16384
#define D_   128
#define M_   (B_*N_)      // 32768
#define KB_  256
#define H_   8
#define HD_  16
#define EPSF 1e-6f

#define OFF_SV (M_*D_)
#define OFF_MK (OFF_SV + B_*258)
#define OFF_ST (OFF_MK + M_)

// ---------------- scratch ----------------
__device__ float g_h   [M_*D_];
__device__ float g_t   [M_*D_];
__device__ float g_fh  [M_*D_];
__device__ float g_acc [M_*D_];
__device__ float g_deg [M_];
__device__ float g_ga  [M_*D_];
__device__ float g_h1  [M_*D_];
__device__ float g_h2  [M_*D_];
__device__ float g_q2  [M_*D_];
__device__ float g_k2  [B_*KB_*D_];
__device__ float g_v2  [B_*KB_*D_];
__device__ float g_oh  [M_*D_];
__device__ float g_hnum [B_*128];
__device__ float g_hmean[B_*128];
__device__ float g_part [B_*8*128];
__device__ float g_Wf  [3*256*128];
__device__ float g_bf  [3*128];
__device__ float g_zero[128];
__device__ float g_A   [(long)B_*N_*N_];   // batched adjacency counts (134MB)

// ---------------- helpers ----------------
__device__ __forceinline__ float to_tf32(float x) {
    uint32_t u;
    asm("cvt.rna.tf32.f32 %0, %1;" : "=r"(u) : "f"(x));
    return __uint_as_float(u);
}

__device__ __forceinline__ void mma_tf32(float c[4], const uint32_t a[4], const uint32_t b[2]) {
    asm volatile(
        "mma.sync.aligned.m16n8k8.row.col.f32.tf32.tf32.f32 "
        "{%0,%1,%2,%3}, {%4,%5,%6,%7}, {%8,%9}, {%0,%1,%2,%3};"
        : "+f"(c[0]), "+f"(c[1]), "+f"(c[2]), "+f"(c[3])
        : "r"(a[0]), "r"(a[1]), "r"(a[2]), "r"(a[3]), "r"(b[0]), "r"(b[1]));
}

// fast exp on FMA pipe: exp(x) = 2^n * P(f), t = x*log2e = n + f, f in [-0.5,0.5]
__device__ __forceinline__ float fexp(float x) {
    x = fmaxf(x, -87.0f);
    float t = x * 1.4426950408889634f;
    float fn = rintf(t);
    float f = t - fn;
    float p = 1.3333558146e-3f;
    p = fmaf(p, f, 9.6179662376e-3f);
    p = fmaf(p, f, 5.5490420128e-2f);
    p = fmaf(p, f, 2.4022650696e-1f);
    p = fmaf(p, f, 6.9314718056e-1f);
    p = fmaf(p, f, 1.0f);
    int n = (int)fn;
    float sc = __int_as_float((n + 127) << 23);
    return p * sc;
}

// ---------------- plain tf32 tensor-core GEMM: C = epi(A@W + bias) -----------
// A virtual concat [A1(lda1) | A2(128, /(deg+eps))]. Optional rowmap gather.
// epi: 0 none, 1 tanh, 3 tanh + gated combine with ga/hres.
__global__ void __launch_bounds__(256, 2) tgemm_k(
    const float* __restrict__ A1, int lda1,
    const float* __restrict__ A2,
    const float* __restrict__ deg,
    const int*   __restrict__ rowmap, int mapMod,
    const float* __restrict__ W, int ldw, int wOff,
    const float* __restrict__ bias, int bOff,
    float* __restrict__ C,
    int K1, int K, int epi,
    const float* __restrict__ ga,
    const float* __restrict__ hres)
{
    __shared__ float As[16][136];
    __shared__ float Bs[16][136];
    const int tid  = threadIdx.x;
    const int m0   = blockIdx.x * 128;
    const int warp = tid >> 5;
    const int lane = tid & 31;
    const int m0w  = (warp >> 2) * 64;
    const int n0w  = (warp & 3) * 32;
    const int g    = lane >> 2;
    const int tig  = lane & 3;

    float c[4][4][4];
    #pragma unroll
    for (int mf = 0; mf < 4; mf++)
        #pragma unroll
        for (int nf = 0; nf < 4; nf++)
            #pragma unroll
            for (int q = 0; q < 4; q++) c[mf][nf][q] = 0.f;

    for (int k0 = 0; k0 < K; k0 += 16) {
        #pragma unroll
        for (int i = 0; i < 2; i++) {
            int idx = tid + i * 256;
            int mr  = idx >> 2;
            int c4  = (idx & 3) * 4;
            int gm  = m0 + mr;
            int pr  = gm;
            if (rowmap) pr = (gm / mapMod) * N_ + rowmap[gm % mapMod];
            int k   = k0 + c4;
            float4 v;
            if (k < K1) {
                v = *(const float4*)&A1[(long)pr * lda1 + k];
            } else {
                v = *(const float4*)&A2[(long)pr * 128 + (k - K1)];
                if (deg) {
                    float s = 1.0f / (deg[pr] + EPSF);
                    v.x *= s; v.y *= s; v.z *= s; v.w *= s;
                }
            }
            As[c4 + 0][mr] = to_tf32(v.x); As[c4 + 1][mr] = to_tf32(v.y);
            As[c4 + 2][mr] = to_tf32(v.z); As[c4 + 3][mr] = to_tf32(v.w);
        }
        #pragma unroll
        for (int i = 0; i < 2; i++) {
            int idx = tid + i * 256;
            int kr  = idx >> 5;
            int c4  = (idx & 31) * 4;
            float4 v = *(const float4*)&W[(long)(k0 + kr) * ldw + wOff + c4];
            Bs[kr][c4 + 0] = to_tf32(v.x); Bs[kr][c4 + 1] = to_tf32(v.y);
            Bs[kr][c4 + 2] = to_tf32(v.z); Bs[kr][c4 + 3] = to_tf32(v.w);
        }
        __syncthreads();
        #pragma unroll
        for (int kk = 0; kk < 2; kk++) {
            int kb = kk * 8;
            uint32_t b[4][2];
            #pragma unroll
            for (int nf = 0; nf < 4; nf++) {
                int nc = n0w + nf * 8 + g;
                b[nf][0] = __float_as_uint(Bs[kb + tig    ][nc]);
                b[nf][1] = __float_as_uint(Bs[kb + tig + 4][nc]);
            }
            #pragma unroll
            for (int mf = 0; mf < 4; mf++) {
                int mcol = m0w + mf * 16 + g;
                uint32_t a[4];
                a[0] = __float_as_uint(As[kb + tig    ][mcol]);
                a[1] = __float_as_uint(As[kb + tig    ][mcol + 8]);
                a[2] = __float_as_uint(As[kb + tig + 4][mcol]);
                a[3] = __float_as_uint(As[kb + tig + 4][mcol + 8]);
                #pragma unroll
                for (int nf = 0; nf < 4; nf++)
                    mma_tf32(c[mf][nf], a, b[nf]);
            }
        }
        __syncthreads();
    }
    #pragma unroll
    for (int mf = 0; mf < 4; mf++) {
        int row0 = m0 + m0w + mf * 16 + g;
        #pragma unroll
        for (int nf = 0; nf < 4; nf++) {
            int col = n0w + nf * 8 + 2 * tig;
            float b0 = bias[bOff + col], b1 = bias[bOff + col + 1];
            float v00 = c[mf][nf][0] + b0, v01 = c[mf][nf][1] + b1;
            float v10 = c[mf][nf][2] + b0, v11 = c[mf][nf][3] + b1;
            if (epi >= 1) { v00 = tanhf(v00); v01 = tanhf(v01); v10 = tanhf(v10); v11 = tanhf(v11); }
            if (epi == 3) {
                long i0 = (long)row0 * 128 + col;
                long i1 = (long)(row0 + 8) * 128 + col;
                float2 g0 = *(const float2*)&ga[i0];
                float2 g1 = *(const float2*)&ga[i1];
                float2 h0 = *(const float2*)&hres[i0];
                float2 h1 = *(const float2*)&hres[i1];
                v00 = g0.x * v00 + (1.f - g0.x) * h0.x;
                v01 = g0.y * v01 + (1.f - g0.y) * h0.y;
                v10 = g1.x * v10 + (1.f - g1.x) * h1.x;
                v11 = g1.y * v11 + (1.f - g1.y) * h1.y;
            }
            *(float2*)&C[(long)row0 * 128 + col]       = make_float2(v00, v01);
            *(float2*)&C[(long)(row0 + 8) * 128 + col] = make_float2(v10, v11);
        }
    }
}

// ---- adjacency aggregation (plain tf32, A exact): acc[b] = A[b] @ fh[b] -----
__global__ void __launch_bounds__(256, 2) adj_tgemm1_k(
    const float* __restrict__ A,
    const float* __restrict__ fh,
    float* __restrict__ acc)
{
    __shared__ float As[16][136];
    __shared__ float Bs[16][136];
    const int tid  = threadIdx.x;
    const int bb   = blockIdx.y;
    const int m0   = blockIdx.x * 128;
    const int warp = tid >> 5;
    const int lane = tid & 31;
    const int m0w  = (warp >> 2) * 64;
    const int n0w  = (warp & 3) * 32;
    const int g    = lane >> 2;
    const int tig  = lane & 3;
    const float* Ab  = A  + (long)bb * N_ * N_;
    const float* fhb = fh + (long)bb * N_ * D_;

    float c[4][4][4];
    #pragma unroll
    for (int mf = 0; mf < 4; mf++)
        #pragma unroll
        for (int nf = 0; nf < 4; nf++)
            #pragma unroll
            for (int q = 0; q < 4; q++) c[mf][nf][q] = 0.f;

    for (int k0 = 0; k0 < N_; k0 += 16) {
        #pragma unroll
        for (int i = 0; i < 2; i++) {
            int idx = tid + i * 256;
            int mr  = idx >> 2;
            int c4  = (idx & 3) * 4;
            float4 v = *(const float4*)&Ab[(long)(m0 + mr) * N_ + k0 + c4];
            As[c4 + 0][mr] = v.x; As[c4 + 1][mr] = v.y;
            As[c4 + 2][mr] = v.z; As[c4 + 3][mr] = v.w;
        }
        #pragma unroll
        for (int i = 0; i < 2; i++) {
            int idx = tid + i * 256;
            int kr  = idx >> 5;
            int c4  = (idx & 31) * 4;
            float4 v = *(const float4*)&fhb[(long)(k0 + kr) * D_ + c4];
            Bs[kr][c4 + 0] = to_tf32(v.x); Bs[kr][c4 + 1] = to_tf32(v.y);
            Bs[kr][c4 + 2] = to_tf32(v.z); Bs[kr][c4 + 3] = to_tf32(v.w);
        }
        __syncthreads();
        #pragma unroll
        for (int kk = 0; kk < 2; kk++) {
            int kb = kk * 8;
            uint32_t b[4][2];
            #pragma unroll
            for (int nf = 0; nf < 4; nf++) {
                int nc = n0w + nf * 8 + g;
                b[nf][0] = __float_as_uint(Bs[kb + tig    ][nc]);
                b[nf][1] = __float_as_uint(Bs[kb + tig + 4][nc]);
            }
            #pragma unroll
            for (int mf = 0; mf < 4; mf++) {
                int mcol = m0w + mf * 16 + g;
                uint32_t a[4];
                a[0] = __float_as_uint(As[kb + tig    ][mcol]);
                a[1] = __float_as_uint(As[kb + tig    ][mcol + 8]);
                a[2] = __float_as_uint(As[kb + tig + 4][mcol]);
                a[3] = __float_as_uint(As[kb + tig + 4][mcol + 8]);
                #pragma unroll
                for (int nf = 0; nf < 4; nf++)
                    mma_tf32(c[mf][nf], a, b[nf]);
            }
        }
        __syncthreads();
    }
    #pragma unroll
    for (int mf = 0; mf < 4; mf++) {
        int row0 = bb * N_ + m0 + m0w + mf * 16 + g;
        #pragma unroll
        for (int nf = 0; nf < 4; nf++) {
            int col = n0w + nf * 8 + 2 * tig;
            *(float2*)&acc[(long)row0 * 128 + col]       = make_float2(c[mf][nf][0], c[mf][nf][1]);
            *(float2*)&acc[(long)(row0 + 8) * 128 + col] = make_float2(c[mf][nf][2], c[mf][nf][3]);
        }
    }
}

// ---------------- scalar fp32 GEMM (exact; tiny/root cases) ------------------
__global__ void __launch_bounds__(256, 2) gemm_k(
    const float* __restrict__ A1, int lda1,
    const float* __restrict__ W, int ldw, int wOff,
    const float* __restrict__ bias, int bOff,
    float* __restrict__ C,
    int K,
    int epi, const float* __restrict__ pos)
{
    __shared__ float As[16][128];
    __shared__ float Bs[16][128];
    const int tid = threadIdx.x;
    const int m0  = blockIdx.x * 128;
    const int ty  = tid >> 4;
    const int tx  = tid & 15;

    float acc[8][8];
    #pragma unroll
    for (int i = 0; i < 8; i++)
        #pragma unroll
        for (int j = 0; j < 8; j++) acc[i][j] = 0.f;

    for (int k0 = 0; k0 < K; k0 += 16) {
        #pragma unroll
        for (int i = 0; i < 2; i++) {
            int idx = tid + i * 256;
            int mr  = idx >> 2;
            int c4  = (idx & 3) * 4;
            float4 v = *(const float4*)&A1[(long)(m0 + mr) * lda1 + k0 + c4];
            As[c4 + 0][mr] = v.x; As[c4 + 1][mr] = v.y;
            As[c4 + 2][mr] = v.z; As[c4 + 3][mr] = v.w;
        }
        #pragma unroll
        for (int i = 0; i < 2; i++) {
            int idx = tid + i * 256;
            int kr  = idx >> 5;
            int c4  = (idx & 31) * 4;
            float4 v = *(const float4*)&W[(long)(k0 + kr) * ldw + wOff + c4];
            *(float4*)&Bs[kr][c4] = v;
        }
        __syncthreads();
        #pragma unroll
        for (int kk = 0; kk < 16; kk++) {
            float a[8], b[8];
            #pragma unroll
            for (int i = 0; i < 8; i++) a[i] = As[kk][ty * 8 + i];
            #pragma unroll
            for (int j = 0; j < 8; j++) b[j] = Bs[kk][tx * 8 + j];
            #pragma unroll
            for (int i = 0; i < 8; i++)
                #pragma unroll
                for (int j = 0; j < 8; j++)
                    acc[i][j] += a[i] * b[j];
        }
        __syncthreads();
    }
    #pragma unroll
    for (int i = 0; i < 8; i++) {
        int gm = m0 + ty * 8 + i;
        #pragma unroll
        for (int j = 0; j < 8; j++) {
            int col = tx * 8 + j;
            float v = acc[i][j] + bias[bOff + col];
            if (epi >= 1) v = tanhf(v);
            if (epi == 2) v += pos[(gm % N_) * 128 + col];
            C[(long)gm * 128 + col] = v;
        }
    }
}

// ---- build adjacency + degree ------------------------------------------------
__global__ void __launch_bounds__(256) edgebuild_k(
    const int* __restrict__ eidx, float* __restrict__ A, float* __restrict__ deg)
{
    int g = blockIdx.x * 256 + threadIdx.x;
    int b = g / E_;
    long base = (long)b * N_ * N_;
    int e0 = eidx[2 * g];
    int e1 = eidx[2 * g + 1];
    atomicAdd(&A[base + (long)e0 * N_ + e1], 1.0f);
    atomicAdd(&A[base + (long)e1 * N_ + e0], 1.0f);
    atomicAdd(&deg[b * N_ + e0], 1.0f);
    atomicAdd(&deg[b * N_ + e1], 1.0f);
}

// ---------------- small fused kernels ----------------------------------------
__global__ void fused_bias_k(const float* __restrict__ bq,
                             const float* __restrict__ bk,
                             const float* __restrict__ bv,
                             const float* __restrict__ Win,
                             const float* __restrict__ b_in,
                             float* __restrict__ bf)
{
    int s = blockIdx.x;
    int n = threadIdx.x;
    const float* bs = (s == 0) ? bq : (s == 1) ? bk : bv;
    float acc = b_in[s * 128 + n];
    for (int k = 0; k < 128; k++)
        acc += bs[k] * Win[k * 384 + s * 128 + n];
    bf[s * 128 + n] = acc;
}

__global__ void __launch_bounds__(256) hnum_k(
    const float* __restrict__ num,
    const float* __restrict__ W0, const float* __restrict__ b0,
    const float* __restrict__ W1, const float* __restrict__ b1,
    float* __restrict__ out)
{
    __shared__ float sn[32 * 64];
    __shared__ float sh[32 * 256];
    int tid = threadIdx.x;
    for (int i = tid; i < 32 * 64; i += 256) sn[i] = num[i];
    __syncthreads();
    for (int i = tid; i < 32 * 256; i += 256) {
        int r = i >> 8, c = i & 255;
        float a = b0[c];
        for (int k = 0; k < 64; k++) a += sn[r * 64 + k] * W0[k * 256 + c];
        sh[i] = tanhf(a);
    }
    __syncthreads();
    for (int i = tid; i < 32 * 128; i += 256) {
        int r = i >> 7, c = i & 127;
        float a = b1[c];
        for (int k = 0; k < 256; k++) a += sh[r * 256 + k] * W1[k * 128 + c];
        out[i] = tanhf(a);
    }
}

__global__ void zero_k(float* __restrict__ p, long n)
{
    long i = ((long)blockIdx.x * 256 + threadIdx.x) * 4;
    if (i < n) *(float4*)&p[i] = make_float4(0.f, 0.f, 0.f, 0.f);
}

// ---------------- attention: 1 row/thread, broadcast K/V, poly exp -----------
__global__ void __launch_bounds__(256) attn2_k(
    const float* __restrict__ q2,
    const float* __restrict__ k2,
    const float* __restrict__ v2,
    float* __restrict__ oh)
{
    __shared__ float Ks[256][16];
    __shared__ float Vs[256][16];
    int qt = blockIdx.x, h = blockIdx.y, b = blockIdx.z;
    int tid = threadIdx.x;

    #pragma unroll
    for (int i = 0; i < 4; i++) {
        int idx = tid + i * 256;
        int j  = idx >> 2;
        int d4 = (idx & 3) * 4;
        *(float4*)&Ks[j][d4] = *(const float4*)&k2[(long)(b * KB_ + j) * D_ + h * HD_ + d4];
        *(float4*)&Vs[j][d4] = *(const float4*)&v2[(long)(b * KB_ + j) * D_ + h * HD_ + d4];
    }
    __syncthreads();

    int qi = qt * 256 + tid;
    const float* qp = &q2[(long)(b * N_ + qi) * D_ + h * HD_];
    float q[16];
    #pragma unroll
    for (int d = 0; d < 16; d += 4) {
        float4 v = *(const float4*)&qp[d];
        q[d] = v.x * 0.25f; q[d+1] = v.y * 0.25f; q[d+2] = v.z * 0.25f; q[d+3] = v.w * 0.25f;
    }

    float m = -1e30f, sum = 0.f;
    float o[16];
    #pragma unroll
    for (int d = 0; d < 16; d++) o[d] = 0.f;

    for (int jj = 0; jj < 256; jj++) {
        float s = 0.f;
        float kreg[16];
        #pragma unroll
        for (int d4 = 0; d4 < 16; d4 += 4) {
            float4 kv = *(const float4*)&Ks[jj][d4];
            kreg[d4] = kv.x; kreg[d4+1] = kv.y; kreg[d4+2] = kv.z; kreg[d4+3] = kv.w;
        }
        #pragma unroll
        for (int d = 0; d < 16; d++) s = fmaf(q[d], kreg[d], s);
        float p;
        if (s > m) {
            float c = fexp(m - s);
            sum *= c;
            #pragma unroll
            for (int d = 0; d < 16; d++) o[d] *= c;
            m = s;
            p = 1.0f;
        } else {
            p = fexp(s - m);
        }
        sum += p;
        #pragma unroll
        for (int d4 = 0; d4 < 16; d4 += 4) {
            float4 vv = *(const float4*)&Vs[jj][d4];
            o[d4]   = fmaf(p, vv.x, o[d4]);
            o[d4+1] = fmaf(p, vv.y, o[d4+1]);
            o[d4+2] = fmaf(p, vv.z, o[d4+2]);
            o[d4+3] = fmaf(p, vv.w, o[d4+3]);
        }
    }
    float inv = 1.0f / sum;
    float* op = &oh[(long)(b * N_ + qi) * D_ + h * HD_];
    #pragma unroll
    for (int d = 0; d < 16; d += 4)
        *(float4*)&op[d] = make_float4(o[d]*inv, o[d+1]*inv, o[d+2]*inv, o[d+3]*inv);
}

// ---------------- mean + tail -------------------------------------------------
__global__ void mean1_k(const float* __restrict__ att, float* __restrict__ part)
{
    int b = blockIdx.x, ch = blockIdx.y, c = threadIdx.x;
    float s = 0.f;
    int n0 = ch * 128;
    for (int n = n0; n < n0 + 128; n++)
        s += att[(long)(b * N_ + n) * D_ + c];
    part[(b * 8 + ch) * 128 + c] = s;
}

__global__ void mean2_k(const float* __restrict__ part, float* __restrict__ hmean)
{
    int b = blockIdx.x, c = threadIdx.x;
    float s = 0.f;
    #pragma unroll
    for (int ch = 0; ch < 8; ch++)
        s += part[(b * 8 + ch) * 128 + c];
    hmean[b * 128 + c] = s * (1.0f / N_);
}

__global__ void tail_k(const float* __restrict__ hnum,
                       const float* __restrict__ hmean,
                       const float* __restrict__ stage,
                       float* __restrict__ out)
{
    int i = blockIdx.x * 256 + threadIdx.x;
    if (i < B_ * 258) {
        int b = i / 258, c = i % 258;
        float v = (c < 128) ? hnum[b * 128 + c]
                : (c < 256) ? hmean[b * 128 + (c - 128)]
                            : stage[b * 2 + (c - 256)];
        out[OFF_SV + i] = v;
    }
    if (i < M_) out[OFF_MK + i] = 1.0f;
    if (i < B_ * 2) out[OFF_ST + i] = stage[i];
}

// ---------------- launcher ----------------------------------------------------
extern "C" void kernel_launch(void* const* d_in, const int* in_sizes, int n_in,
                              void* d_out, int out_size)
{
    const float* numerical   = (const float*)d_in[0];
    const float* node_feat   = (const float*)d_in[1];
    const float* stage       = (const float*)d_in[2];
    const float* W_num0      = (const float*)d_in[3];
    const float* b_num0      = (const float*)d_in[4];
    const float* W_num1      = (const float*)d_in[5];
    const float* b_num1      = (const float*)d_in[6];
    const float* W_node      = (const float*)d_in[7];
    const float* b_node      = (const float*)d_in[8];
    const float* pos_enc     = (const float*)d_in[9];
    const float* ew1         = (const float*)d_in[10];
    const float* eb1         = (const float*)d_in[11];
    const float* ew2         = (const float*)d_in[12];
    const float* eb2         = (const float*)d_in[13];
    const float* Wg          = (const float*)d_in[14];
    const float* bg          = (const float*)d_in[15];
    const float* Wu          = (const float*)d_in[16];
    const float* bu          = (const float*)d_in[17];
    const float* Wq1         = (const float*)d_in[18];
    const float* bq1         = (const float*)d_in[19];
    const float* Wk1         = (const float*)d_in[20];
    const float* bk1         = (const float*)d_in[21];
    const float* Wv1         = (const float*)d_in[22];
    const float* bv1         = (const float*)d_in[23];
    const float* Win         = (const float*)d_in[24];
    const float* b_in        = (const float*)d_in[25];
    const float* Wout        = (const float*)d_in[26];
    const float* b_out       = (const float*)d_in[27];
    const int*   ei_dis      = (const int*)d_in[28];
    const int*   ei_od       = (const int*)d_in[29];
    const int*   build_idx   = (const int*)d_in[31];
    float* out = (float*)d_out;

    float *p_h, *p_t, *p_fh, *p_acc, *p_deg, *p_ga, *p_h1, *p_h2;
    float *p_q2, *p_k2, *p_v2, *p_oh, *p_hnum, *p_hmean, *p_part, *p_Wf, *p_bf, *p_zero, *p_A;
    cudaGetSymbolAddress((void**)&p_h,    g_h);
    cudaGetSymbolAddress((void**)&p_t,    g_t);
    cudaGetSymbolAddress((void**)&p_fh,   g_fh);
    cudaGetSymbolAddress((void**)&p_acc,  g_acc);
    cudaGetSymbolAddress((void**)&p_deg,  g_deg);
    cudaGetSymbolAddress((void**)&p_ga,   g_ga);
    cudaGetSymbolAddress((void**)&p_h1,   g_h1);
    cudaGetSymbolAddress((void**)&p_h2,   g_h2);
    cudaGetSymbolAddress((void**)&p_q2,   g_q2);
    cudaGetSymbolAddress((void**)&p_k2,   g_k2);
    cudaGetSymbolAddress((void**)&p_v2,   g_v2);
    cudaGetSymbolAddress((void**)&p_oh,   g_oh);
    cudaGetSymbolAddress((void**)&p_hnum, g_hnum);
    cudaGetSymbolAddress((void**)&p_hmean,g_hmean);
    cudaGetSymbolAddress((void**)&p_part, g_part);
    cudaGetSymbolAddress((void**)&p_Wf,   g_Wf);
    cudaGetSymbolAddress((void**)&p_bf,   g_bf);
    cudaGetSymbolAddress((void**)&p_zero, g_zero);
    cudaGetSymbolAddress((void**)&p_A,    g_A);

    // fused attention projection weights: Wf = W{q,k,v}1[256,128] @ Win-slice[128,128]
    // K = 128 (inner dim)  — FIXED from round 6's erroneous K=256
    gemm_k<<<2, 256>>>(Wq1, 128, Win, 384, 0,   p_zero, 0, p_Wf,         128, 0, nullptr);
    gemm_k<<<2, 256>>>(Wk1, 128, Win, 384, 128, p_zero, 0, p_Wf + 32768, 128, 0, nullptr);
    gemm_k<<<2, 256>>>(Wv1, 128, Win, 384, 256, p_zero, 0, p_Wf + 65536, 128, 0, nullptr);
    fused_bias_k<<<3, 128>>>(bq1, bk1, bv1, Win, b_in, p_bf);

    hnum_k<<<1, 256>>>(numerical, W_num0, b_num0, W_num1, b_num1, p_hnum);

    // h = tanh(node_feature @ W_node + b_node) + pos_enc (fp32 root)
    gemm_k<<<256, 256>>>(node_feat, 32, W_node, 128, 0, b_node, 0, p_h, 32, 2, pos_enc);

    // two message-passing branches (last GCN layer only)
    for (int L = 0; L < 2; L++) {
        const float* ew = L ? ew2 : ew1;
        const float* eb = L ? eb2 : eb1;
        const int*   ei = L ? ei_od : ei_dis;
        float* hout = L ? p_h2 : p_h1;
        tgemm_k<<<256, 256>>>(p_h, 128, nullptr, nullptr, nullptr, 0,
                              ew + 32768, 128, 0, eb, 256, p_t, 128, 128, 1, nullptr, nullptr);
        tgemm_k<<<256, 256>>>(p_t, 128, nullptr, nullptr, nullptr, 0,
                              ew + 49152, 128, 0, eb, 384, p_fh, 128, 128, 1, nullptr, nullptr);
        zero_k<<<(int)(((long)B_*N_*N_)/1024), 256>>>(p_A, (long)B_*N_*N_);
        zero_k<<<M_/1024, 256>>>(p_deg, M_);
        edgebuild_k<<<B_*E_/256, 256>>>(ei, p_A, p_deg);
        adj_tgemm1_k<<<dim3(8, 32), 256>>>(p_A, p_fh, p_acc);
        tgemm_k<<<256, 256>>>(p_h, 128, p_acc, p_deg, nullptr, 0,
                              Wg, 128, 0, bg, 0, p_ga, 128, 256, 1, nullptr, nullptr);
        // update GEMM with fused gated combine -> hout
        tgemm_k<<<256, 256>>>(p_h, 128, p_acc, p_deg, nullptr, 0,
                              Wu, 128, 0, bu, 0, hout, 128, 256, 3, p_ga, p_h);
    }

    // q2 / k2 / v2 projections (all tensor-core)
    tgemm_k<<<256, 256>>>(p_h1, 128, p_h2, nullptr, nullptr, 0,
                          p_Wf, 128, 0, p_bf, 0, p_q2, 128, 256, 0, nullptr, nullptr);
    tgemm_k<<<64, 256>>>(p_h1, 128, p_h2, nullptr, build_idx, 256,
                         p_Wf + 32768, 128, 0, p_bf, 128, p_k2, 128, 256, 0, nullptr, nullptr);
    tgemm_k<<<64, 256>>>(p_h1, 128, p_h2, nullptr, build_idx, 256,
                         p_Wf + 65536, 128, 0, p_bf, 256, p_v2, 128, 256, 0, nullptr, nullptr);

    // attention
    attn2_k<<<dim3(4, H_, B_), 256>>>(p_q2, p_k2, p_v2, p_oh);

    // h_att = oh @ W_out + b_out
    tgemm_k<<<256, 256>>>(p_oh, 128, nullptr, nullptr, nullptr, 0,
                          Wout, 128, 0, b_out, 0, out, 128, 128, 0, nullptr, nullptr);

    // mean + tail
    mean1_k<<<dim3(32, 8), 128>>>(out, p_part);
    mean2_k<<<32, 128>>>(p_part, p_hmean);
    tail_k<<<129, 256>>>(p_hnum, p_hmean, stage, out);

    (void)in_sizes; (void)n_in; (void)out_size;
}

// round 9
// speedup vs baseline: 2.1210x; 1.1179x over previous
#include <cuda_runtime.h>
#include <cuda_bf16.h>
#include <math.h>
#include <stdint.h>

// Problem constants
#define B_   32
#define N_   1024
#define E_   16384
#define D_   128
#define M_   (B_*N_)      // 32768
#define KB_  256
#define H_   8
#define HD_  16
#define EPSF 1e-6f

#define OFF_SV (M_*D_)
#define OFF_MK (OFF_SV + B_*258)
#define OFF_ST (OFF_MK + M_)

// ---------------- scratch ----------------
__device__ float g_h   [M_*D_];
__device__ float g_t   [M_*D_];
__device__ float g_fhb [2*M_*D_];
__device__ float g_accb[2*M_*D_];
__device__ float g_degb[2*M_];
__device__ float g_hb  [2*M_*D_];     // gated outputs h1|h2 (contiguous)
__device__ float g_q2  [M_*D_];
__device__ float g_k2  [B_*KB_*D_];
__device__ float g_v2  [B_*KB_*D_];
__device__ float g_oh  [M_*D_];
__device__ float g_hnum [B_*128];
__device__ float g_hmean[B_*128];
__device__ float g_part [B_*8*128];
__device__ float g_Wf  [3*256*128];
__device__ float g_bf  [3*128];
__device__ float g_zero[128];
__device__ __nv_bfloat16 g_Abf[2L*B_*N_*N_];   // adjacency counts, bf16, both branches (134MB)

// ---------------- helpers ----------------
__device__ __forceinline__ float to_tf32(float x) {
    uint32_t u;
    asm("cvt.rna.tf32.f32 %0, %1;" : "=r"(u) : "f"(x));
    return __uint_as_float(u);
}

__device__ __forceinline__ void mma_tf32(float c[4], const uint32_t a[4], const uint32_t b[2]) {
    asm volatile(
        "mma.sync.aligned.m16n8k8.row.col.f32.tf32.tf32.f32 "
        "{%0,%1,%2,%3}, {%4,%5,%6,%7}, {%8,%9}, {%0,%1,%2,%3};"
        : "+f"(c[0]), "+f"(c[1]), "+f"(c[2]), "+f"(c[3])
        : "r"(a[0]), "r"(a[1]), "r"(a[2]), "r"(a[3]), "r"(b[0]), "r"(b[1]));
}

// fast exp on FMA pipe: exp(x) = 2^n * P(f), P(f)~=2^f, f in [-0.5,0.5]
__device__ __forceinline__ float fexp(float x) {
    x = fmaxf(x, -87.0f);
    float t = x * 1.4426950408889634f;
    float fn = rintf(t);
    float f = t - fn;
    float p = 1.3333558146e-3f;
    p = fmaf(p, f, 9.6179662376e-3f);
    p = fmaf(p, f, 5.5490420128e-2f);
    p = fmaf(p, f, 2.4022650696e-1f);
    p = fmaf(p, f, 6.9314718056e-1f);
    p = fmaf(p, f, 1.0f);
    int n = (int)fn;
    float sc = __int_as_float((n + 127) << 23);
    return p * sc;
}

// ---------------- plain tf32 tensor-core GEMM: C = epi(A@W + bias) -----------
// A virtual concat [A1(lda1) | A2(128, /(deg+eps))]. Optional rowmap gather.
// epi: 0 none, 1 tanh.
__global__ void __launch_bounds__(256, 2) tgemm_k(
    const float* __restrict__ A1, int lda1,
    const float* __restrict__ A2,
    const float* __restrict__ deg,
    const int*   __restrict__ rowmap, int mapMod,
    const float* __restrict__ W, int ldw, int wOff,
    const float* __restrict__ bias, int bOff,
    float* __restrict__ C,
    int K1, int K, int epi)
{
    __shared__ float As[16][136];
    __shared__ float Bs[16][136];
    const int tid  = threadIdx.x;
    const int m0   = blockIdx.x * 128;
    const int warp = tid >> 5;
    const int lane = tid & 31;
    const int m0w  = (warp >> 2) * 64;
    const int n0w  = (warp & 3) * 32;
    const int g    = lane >> 2;
    const int tig  = lane & 3;

    float c[4][4][4];
    #pragma unroll
    for (int mf = 0; mf < 4; mf++)
        #pragma unroll
        for (int nf = 0; nf < 4; nf++)
            #pragma unroll
            for (int q = 0; q < 4; q++) c[mf][nf][q] = 0.f;

    for (int k0 = 0; k0 < K; k0 += 16) {
        #pragma unroll
        for (int i = 0; i < 2; i++) {
            int idx = tid + i * 256;
            int mr  = idx >> 2;
            int c4  = (idx & 3) * 4;
            int gm  = m0 + mr;
            int pr  = gm;
            if (rowmap) pr = (gm / mapMod) * N_ + rowmap[gm % mapMod];
            int k   = k0 + c4;
            float4 v;
            if (k < K1) {
                v = *(const float4*)&A1[(long)pr * lda1 + k];
            } else {
                v = *(const float4*)&A2[(long)pr * 128 + (k - K1)];
                if (deg) {
                    float s = 1.0f / (deg[pr] + EPSF);
                    v.x *= s; v.y *= s; v.z *= s; v.w *= s;
                }
            }
            As[c4 + 0][mr] = to_tf32(v.x); As[c4 + 1][mr] = to_tf32(v.y);
            As[c4 + 2][mr] = to_tf32(v.z); As[c4 + 3][mr] = to_tf32(v.w);
        }
        #pragma unroll
        for (int i = 0; i < 2; i++) {
            int idx = tid + i * 256;
            int kr  = idx >> 5;
            int c4  = (idx & 31) * 4;
            float4 v = *(const float4*)&W[(long)(k0 + kr) * ldw + wOff + c4];
            Bs[kr][c4 + 0] = to_tf32(v.x); Bs[kr][c4 + 1] = to_tf32(v.y);
            Bs[kr][c4 + 2] = to_tf32(v.z); Bs[kr][c4 + 3] = to_tf32(v.w);
        }
        __syncthreads();
        #pragma unroll
        for (int kk = 0; kk < 2; kk++) {
            int kb = kk * 8;
            uint32_t b[4][2];
            #pragma unroll
            for (int nf = 0; nf < 4; nf++) {
                int nc = n0w + nf * 8 + g;
                b[nf][0] = __float_as_uint(Bs[kb + tig    ][nc]);
                b[nf][1] = __float_as_uint(Bs[kb + tig + 4][nc]);
            }
            #pragma unroll
            for (int mf = 0; mf < 4; mf++) {
                int mcol = m0w + mf * 16 + g;
                uint32_t a[4];
                a[0] = __float_as_uint(As[kb + tig    ][mcol]);
                a[1] = __float_as_uint(As[kb + tig    ][mcol + 8]);
                a[2] = __float_as_uint(As[kb + tig + 4][mcol]);
                a[3] = __float_as_uint(As[kb + tig + 4][mcol + 8]);
                #pragma unroll
                for (int nf = 0; nf < 4; nf++)
                    mma_tf32(c[mf][nf], a, b[nf]);
            }
        }
        __syncthreads();
    }
    #pragma unroll
    for (int mf = 0; mf < 4; mf++) {
        int row0 = m0 + m0w + mf * 16 + g;
        #pragma unroll
        for (int nf = 0; nf < 4; nf++) {
            int col = n0w + nf * 8 + 2 * tig;
            float b0 = bias[bOff + col], b1 = bias[bOff + col + 1];
            float v00 = c[mf][nf][0] + b0, v01 = c[mf][nf][1] + b1;
            float v10 = c[mf][nf][2] + b0, v11 = c[mf][nf][3] + b1;
            if (epi >= 1) { v00 = tanhf(v00); v01 = tanhf(v01); v10 = tanhf(v10); v11 = tanhf(v11); }
            *(float2*)&C[(long)row0 * 128 + col]       = make_float2(v00, v01);
            *(float2*)&C[(long)(row0 + 8) * 128 + col] = make_float2(v10, v11);
        }
    }
}

// ---- fused gate+update+combine dual GEMM ------------------------------------
// For branch bz: A = [h | acc/(deg+eps)] (K=256), computes
//   gate = tanh(A@Wg+bg), upd = tanh(A@Wu+bu), hout = gate*upd + (1-gate)*h
// M-tile 64, N=256 (128 gate cols + 128 update cols interleaved by warp group).
__global__ void __launch_bounds__(256, 2) gu_k(
    const float* __restrict__ h,
    const float* __restrict__ accb,
    const float* __restrict__ degb,
    const float* __restrict__ Wg, const float* __restrict__ bg,
    const float* __restrict__ Wu, const float* __restrict__ bu,
    float* __restrict__ houtb)
{
    const int br = blockIdx.y;
    const float* acc  = accb + (long)br * M_ * D_;
    const float* deg  = degb + br * M_;
    float*       hout = houtb + (long)br * M_ * D_;

    __shared__ float As [16][72];
    __shared__ float BsG[16][136];
    __shared__ float BsU[16][136];
    const int tid  = threadIdx.x;
    const int m0   = blockIdx.x * 64;
    const int warp = tid >> 5;
    const int lane = tid & 31;
    const int m0w  = (warp >> 2) * 32;   // 0 or 32
    const int n0w  = (warp & 3) * 32;    // 0,32,64,96
    const int g    = lane >> 2;
    const int tig  = lane & 3;

    float cg[2][4][4], cu[2][4][4];
    #pragma unroll
    for (int mf = 0; mf < 2; mf++)
        #pragma unroll
        for (int nf = 0; nf < 4; nf++)
            #pragma unroll
            for (int q = 0; q < 4; q++) { cg[mf][nf][q] = 0.f; cu[mf][nf][q] = 0.f; }

    for (int k0 = 0; k0 < 256; k0 += 16) {
        // A tile: 64 rows x 16 k (one float4 per thread)
        {
            int mr = tid >> 2;
            int c4 = (tid & 3) * 4;
            int pr = m0 + mr;
            int k  = k0 + c4;
            float4 v;
            if (k < 128) {
                v = *(const float4*)&h[(long)pr * 128 + k];
            } else {
                v = *(const float4*)&acc[(long)pr * 128 + (k - 128)];
                float s = 1.0f / (deg[pr] + EPSF);
                v.x *= s; v.y *= s; v.z *= s; v.w *= s;
            }
            As[c4 + 0][mr] = to_tf32(v.x); As[c4 + 1][mr] = to_tf32(v.y);
            As[c4 + 2][mr] = to_tf32(v.z); As[c4 + 3][mr] = to_tf32(v.w);
        }
        // B tiles: Wg and Wu, each 16x128
        #pragma unroll
        for (int i = 0; i < 2; i++) {
            int idx = tid + i * 256;
            int kr  = idx >> 5;
            int c4  = (idx & 31) * 4;
            float4 vg = *(const float4*)&Wg[(long)(k0 + kr) * 128 + c4];
            float4 vu = *(const float4*)&Wu[(long)(k0 + kr) * 128 + c4];
            BsG[kr][c4 + 0] = to_tf32(vg.x); BsG[kr][c4 + 1] = to_tf32(vg.y);
            BsG[kr][c4 + 2] = to_tf32(vg.z); BsG[kr][c4 + 3] = to_tf32(vg.w);
            BsU[kr][c4 + 0] = to_tf32(vu.x); BsU[kr][c4 + 1] = to_tf32(vu.y);
            BsU[kr][c4 + 2] = to_tf32(vu.z); BsU[kr][c4 + 3] = to_tf32(vu.w);
        }
        __syncthreads();
        #pragma unroll
        for (int kk = 0; kk < 2; kk++) {
            int kb = kk * 8;
            uint32_t bgf[4][2], buf[4][2];
            #pragma unroll
            for (int nf = 0; nf < 4; nf++) {
                int nc = n0w + nf * 8 + g;
                bgf[nf][0] = __float_as_uint(BsG[kb + tig    ][nc]);
                bgf[nf][1] = __float_as_uint(BsG[kb + tig + 4][nc]);
                buf[nf][0] = __float_as_uint(BsU[kb + tig    ][nc]);
                buf[nf][1] = __float_as_uint(BsU[kb + tig + 4][nc]);
            }
            #pragma unroll
            for (int mf = 0; mf < 2; mf++) {
                int mcol = m0w + mf * 16 + g;
                uint32_t a[4];
                a[0] = __float_as_uint(As[kb + tig    ][mcol]);
                a[1] = __float_as_uint(As[kb + tig    ][mcol + 8]);
                a[2] = __float_as_uint(As[kb + tig + 4][mcol]);
                a[3] = __float_as_uint(As[kb + tig + 4][mcol + 8]);
                #pragma unroll
                for (int nf = 0; nf < 4; nf++) {
                    mma_tf32(cg[mf][nf], a, bgf[nf]);
                    mma_tf32(cu[mf][nf], a, buf[nf]);
                }
            }
        }
        __syncthreads();
    }
    // epilogue: gated combine
    #pragma unroll
    for (int mf = 0; mf < 2; mf++) {
        int row0 = m0 + m0w + mf * 16 + g;
        #pragma unroll
        for (int nf = 0; nf < 4; nf++) {
            int col = n0w + nf * 8 + 2 * tig;
            float bg0 = bg[col], bg1 = bg[col + 1];
            float bu0 = bu[col], bu1 = bu[col + 1];
            float2 h0 = *(const float2*)&h[(long)row0 * 128 + col];
            float2 h1 = *(const float2*)&h[(long)(row0 + 8) * 128 + col];
            float G00 = tanhf(cg[mf][nf][0] + bg0), G01 = tanhf(cg[mf][nf][1] + bg1);
            float G10 = tanhf(cg[mf][nf][2] + bg0), G11 = tanhf(cg[mf][nf][3] + bg1);
            float U00 = tanhf(cu[mf][nf][0] + bu0), U01 = tanhf(cu[mf][nf][1] + bu1);
            float U10 = tanhf(cu[mf][nf][2] + bu0), U11 = tanhf(cu[mf][nf][3] + bu1);
            float2 o0 = make_float2(G00 * U00 + (1.f - G00) * h0.x,
                                    G01 * U01 + (1.f - G01) * h0.y);
            float2 o1 = make_float2(G10 * U10 + (1.f - G10) * h1.x,
                                    G11 * U11 + (1.f - G11) * h1.y);
            *(float2*)&hout[(long)row0 * 128 + col]       = o0;
            *(float2*)&hout[(long)(row0 + 8) * 128 + col] = o1;
        }
    }
}

// ---- adjacency aggregation, bf16 A (exact counts): acc[br][b] = A @ fh ------
__global__ void __launch_bounds__(256, 2) adj_tgemm_k(
    const __nv_bfloat16* __restrict__ Abf,
    const float* __restrict__ fhb,
    float* __restrict__ accb)
{
    __shared__ float As[16][136];
    __shared__ float Bs[16][136];
    const int tid  = threadIdx.x;
    const int bb   = blockIdx.y;
    const int br   = blockIdx.z;
    const int m0   = blockIdx.x * 128;
    const int warp = tid >> 5;
    const int lane = tid & 31;
    const int m0w  = (warp >> 2) * 64;
    const int n0w  = (warp & 3) * 32;
    const int g    = lane >> 2;
    const int tig  = lane & 3;
    const __nv_bfloat16* Ab = Abf + (long)br * B_ * N_ * N_ + (long)bb * N_ * N_;
    const float* fhp = fhb + (long)br * M_ * D_ + (long)bb * N_ * D_;
    float* accp      = accb + (long)br * M_ * D_;

    float c[4][4][4];
    #pragma unroll
    for (int mf = 0; mf < 4; mf++)
        #pragma unroll
        for (int nf = 0; nf < 4; nf++)
            #pragma unroll
            for (int q = 0; q < 4; q++) c[mf][nf][q] = 0.f;

    for (int k0 = 0; k0 < N_; k0 += 16) {
        // A tile: 128 rows x 16 cols bf16; each thread loads 8 bf16 (16B)
        {
            int mr = tid >> 1;
            int c8 = (tid & 1) * 8;
            uint4 raw = *(const uint4*)(Ab + (long)(m0 + mr) * N_ + k0 + c8);
            const __nv_bfloat162* p2 = (const __nv_bfloat162*)&raw;
            #pragma unroll
            for (int j = 0; j < 4; j++) {
                float2 f = __bfloat1622float2(p2[j]);
                As[c8 + 2 * j][mr]     = f.x;
                As[c8 + 2 * j + 1][mr] = f.y;
            }
        }
        #pragma unroll
        for (int i = 0; i < 2; i++) {
            int idx = tid + i * 256;
            int kr  = idx >> 5;
            int c4  = (idx & 31) * 4;
            float4 v = *(const float4*)&fhp[(long)(k0 + kr) * D_ + c4];
            Bs[kr][c4 + 0] = to_tf32(v.x); Bs[kr][c4 + 1] = to_tf32(v.y);
            Bs[kr][c4 + 2] = to_tf32(v.z); Bs[kr][c4 + 3] = to_tf32(v.w);
        }
        __syncthreads();
        #pragma unroll
        for (int kk = 0; kk < 2; kk++) {
            int kb = kk * 8;
            uint32_t b[4][2];
            #pragma unroll
            for (int nf = 0; nf < 4; nf++) {
                int nc = n0w + nf * 8 + g;
                b[nf][0] = __float_as_uint(Bs[kb + tig    ][nc]);
                b[nf][1] = __float_as_uint(Bs[kb + tig + 4][nc]);
            }
            #pragma unroll
            for (int mf = 0; mf < 4; mf++) {
                int mcol = m0w + mf * 16 + g;
                uint32_t a[4];
                a[0] = __float_as_uint(As[kb + tig    ][mcol]);
                a[1] = __float_as_uint(As[kb + tig    ][mcol + 8]);
                a[2] = __float_as_uint(As[kb + tig + 4][mcol]);
                a[3] = __float_as_uint(As[kb + tig + 4][mcol + 8]);
                #pragma unroll
                for (int nf = 0; nf < 4; nf++)
                    mma_tf32(c[mf][nf], a, b[nf]);
            }
        }
        __syncthreads();
    }
    #pragma unroll
    for (int mf = 0; mf < 4; mf++) {
        int row0 = bb * N_ + m0 + m0w + mf * 16 + g;
        #pragma unroll
        for (int nf = 0; nf < 4; nf++) {
            int col = n0w + nf * 8 + 2 * tig;
            *(float2*)&accp[(long)row0 * 128 + col]       = make_float2(c[mf][nf][0], c[mf][nf][1]);
            *(float2*)&accp[(long)(row0 + 8) * 128 + col] = make_float2(c[mf][nf][2], c[mf][nf][3]);
        }
    }
}

// ---------------- scalar fp32 GEMM (exact; tiny/root cases) ------------------
__global__ void __launch_bounds__(256, 2) gemm_k(
    const float* __restrict__ A1, int lda1,
    const float* __restrict__ W, int ldw, int wOff,
    const float* __restrict__ bias, int bOff,
    float* __restrict__ C,
    int K,
    int epi, const float* __restrict__ pos)
{
    __shared__ float As[16][128];
    __shared__ float Bs[16][128];
    const int tid = threadIdx.x;
    const int m0  = blockIdx.x * 128;
    const int ty  = tid >> 4;
    const int tx  = tid & 15;

    float acc[8][8];
    #pragma unroll
    for (int i = 0; i < 8; i++)
        #pragma unroll
        for (int j = 0; j < 8; j++) acc[i][j] = 0.f;

    for (int k0 = 0; k0 < K; k0 += 16) {
        #pragma unroll
        for (int i = 0; i < 2; i++) {
            int idx = tid + i * 256;
            int mr  = idx >> 2;
            int c4  = (idx & 3) * 4;
            float4 v = *(const float4*)&A1[(long)(m0 + mr) * lda1 + k0 + c4];
            As[c4 + 0][mr] = v.x; As[c4 + 1][mr] = v.y;
            As[c4 + 2][mr] = v.z; As[c4 + 3][mr] = v.w;
        }
        #pragma unroll
        for (int i = 0; i < 2; i++) {
            int idx = tid + i * 256;
            int kr  = idx >> 5;
            int c4  = (idx & 31) * 4;
            float4 v = *(const float4*)&W[(long)(k0 + kr) * ldw + wOff + c4];
            *(float4*)&Bs[kr][c4] = v;
        }
        __syncthreads();
        #pragma unroll
        for (int kk = 0; kk < 16; kk++) {
            float a[8], b[8];
            #pragma unroll
            for (int i = 0; i < 8; i++) a[i] = As[kk][ty * 8 + i];
            #pragma unroll
            for (int j = 0; j < 8; j++) b[j] = Bs[kk][tx * 8 + j];
            #pragma unroll
            for (int i = 0; i < 8; i++)
                #pragma unroll
                for (int j = 0; j < 8; j++)
                    acc[i][j] += a[i] * b[j];
        }
        __syncthreads();
    }
    #pragma unroll
    for (int i = 0; i < 8; i++) {
        int gm = m0 + ty * 8 + i;
        #pragma unroll
        for (int j = 0; j < 8; j++) {
            int col = tx * 8 + j;
            float v = acc[i][j] + bias[bOff + col];
            if (epi >= 1) v = tanhf(v);
            if (epi == 2) v += pos[(gm % N_) * 128 + col];
            C[(long)gm * 128 + col] = v;
        }
    }
}

// ---- build adjacency (bf16) + degree, both branches -------------------------
__global__ void __launch_bounds__(256) edgebuild2_k(
    const int* __restrict__ ei0, const int* __restrict__ ei1,
    __nv_bfloat16* __restrict__ Abf, float* __restrict__ degb)
{
    int gidx = blockIdx.x * 256 + threadIdx.x;   // 0 .. 2*B*E
    int br = gidx / (B_ * E_);
    int e  = gidx % (B_ * E_);
    const int* ei = br ? ei1 : ei0;
    int b = e / E_;
    long base = (long)br * B_ * N_ * N_ + (long)b * N_ * N_;
    int e0 = ei[2 * e];
    int e1 = ei[2 * e + 1];
    __nv_bfloat16 one = __float2bfloat16(1.0f);
    atomicAdd(&Abf[base + (long)e0 * N_ + e1], one);
    atomicAdd(&Abf[base + (long)e1 * N_ + e0], one);
    atomicAdd(&degb[br * M_ + b * N_ + e0], 1.0f);
    atomicAdd(&degb[br * M_ + b * N_ + e1], 1.0f);
}

// ---------------- small fused kernels ----------------------------------------
__global__ void fused_bias_k(const float* __restrict__ bq,
                             const float* __restrict__ bk,
                             const float* __restrict__ bv,
                             const float* __restrict__ Win,
                             const float* __restrict__ b_in,
                             float* __restrict__ bf)
{
    int s = blockIdx.x;
    int n = threadIdx.x;
    const float* bs = (s == 0) ? bq : (s == 1) ? bk : bv;
    float acc = b_in[s * 128 + n];
    for (int k = 0; k < 128; k++)
        acc += bs[k] * Win[k * 384 + s * 128 + n];
    bf[s * 128 + n] = acc;
}

__global__ void __launch_bounds__(256) hnum_k(
    const float* __restrict__ num,
    const float* __restrict__ W0, const float* __restrict__ b0,
    const float* __restrict__ W1, const float* __restrict__ b1,
    float* __restrict__ out)
{
    __shared__ float sn[32 * 64];
    __shared__ float sh[32 * 256];
    int tid = threadIdx.x;
    for (int i = tid; i < 32 * 64; i += 256) sn[i] = num[i];
    __syncthreads();
    for (int i = tid; i < 32 * 256; i += 256) {
        int r = i >> 8, c = i & 255;
        float a = b0[c];
        for (int k = 0; k < 64; k++) a += sn[r * 64 + k] * W0[k * 256 + c];
        sh[i] = tanhf(a);
    }
    __syncthreads();
    for (int i = tid; i < 32 * 128; i += 256) {
        int r = i >> 7, c = i & 127;
        float a = b1[c];
        for (int k = 0; k < 256; k++) a += sh[r * 256 + k] * W1[k * 128 + c];
        out[i] = tanhf(a);
    }
}

__global__ void zero_k(float* __restrict__ p, long n)
{
    long i = ((long)blockIdx.x * 256 + threadIdx.x) * 4;
    if (i < n) *(float4*)&p[i] = make_float4(0.f, 0.f, 0.f, 0.f);
}

// ---------------- attention: 1 row/thread, broadcast K/V, poly exp -----------
__global__ void __launch_bounds__(256) attn2_k(
    const float* __restrict__ q2,
    const float* __restrict__ k2,
    const float* __restrict__ v2,
    float* __restrict__ oh)
{
    __shared__ float Ks[256][16];
    __shared__ float Vs[256][16];
    int qt = blockIdx.x, h = blockIdx.y, b = blockIdx.z;
    int tid = threadIdx.x;

    #pragma unroll
    for (int i = 0; i < 4; i++) {
        int idx = tid + i * 256;
        int j  = idx >> 2;
        int d4 = (idx & 3) * 4;
        *(float4*)&Ks[j][d4] = *(const float4*)&k2[(long)(b * KB_ + j) * D_ + h * HD_ + d4];
        *(float4*)&Vs[j][d4] = *(const float4*)&v2[(long)(b * KB_ + j) * D_ + h * HD_ + d4];
    }
    __syncthreads();

    int qi = qt * 256 + tid;
    const float* qp = &q2[(long)(b * N_ + qi) * D_ + h * HD_];
    float q[16];
    #pragma unroll
    for (int d = 0; d < 16; d += 4) {
        float4 v = *(const float4*)&qp[d];
        q[d] = v.x * 0.25f; q[d+1] = v.y * 0.25f; q[d+2] = v.z * 0.25f; q[d+3] = v.w * 0.25f;
    }

    float m = -1e30f, sum = 0.f;
    float o[16];
    #pragma unroll
    for (int d = 0; d < 16; d++) o[d] = 0.f;

    for (int jj = 0; jj < 256; jj++) {
        float s = 0.f;
        float kreg[16];
        #pragma unroll
        for (int d4 = 0; d4 < 16; d4 += 4) {
            float4 kv = *(const float4*)&Ks[jj][d4];
            kreg[d4] = kv.x; kreg[d4+1] = kv.y; kreg[d4+2] = kv.z; kreg[d4+3] = kv.w;
        }
        #pragma unroll
        for (int d = 0; d < 16; d++) s = fmaf(q[d], kreg[d], s);
        float p;
        if (s > m) {
            float c = fexp(m - s);
            sum *= c;
            #pragma unroll
            for (int d = 0; d < 16; d++) o[d] *= c;
            m = s;
            p = 1.0f;
        } else {
            p = fexp(s - m);
        }
        sum += p;
        #pragma unroll
        for (int d4 = 0; d4 < 16; d4 += 4) {
            float4 vv = *(const float4*)&Vs[jj][d4];
            o[d4]   = fmaf(p, vv.x, o[d4]);
            o[d4+1] = fmaf(p, vv.y, o[d4+1]);
            o[d4+2] = fmaf(p, vv.z, o[d4+2]);
            o[d4+3] = fmaf(p, vv.w, o[d4+3]);
        }
    }
    float inv = 1.0f / sum;
    float* op = &oh[(long)(b * N_ + qi) * D_ + h * HD_];
    #pragma unroll
    for (int d = 0; d < 16; d += 4)
        *(float4*)&op[d] = make_float4(o[d]*inv, o[d+1]*inv, o[d+2]*inv, o[d+3]*inv);
}

// ---------------- mean + tail -------------------------------------------------
__global__ void mean1_k(const float* __restrict__ att, float* __restrict__ part)
{
    int b = blockIdx.x, ch = blockIdx.y, c = threadIdx.x;
    float s = 0.f;
    int n0 = ch * 128;
    for (int n = n0; n < n0 + 128; n++)
        s += att[(long)(b * N_ + n) * D_ + c];
    part[(b * 8 + ch) * 128 + c] = s;
}

__global__ void mean2_k(const float* __restrict__ part, float* __restrict__ hmean)
{
    int b = blockIdx.x, c = threadIdx.x;
    float s = 0.f;
    #pragma unroll
    for (int ch = 0; ch < 8; ch++)
        s += part[(b * 8 + ch) * 128 + c];
    hmean[b * 128 + c] = s * (1.0f / N_);
}

__global__ void tail_k(const float* __restrict__ hnum,
                       const float* __restrict__ hmean,
                       const float* __restrict__ stage,
                       float* __restrict__ out)
{
    int i = blockIdx.x * 256 + threadIdx.x;
    if (i < B_ * 258) {
        int b = i / 258, c = i % 258;
        float v = (c < 128) ? hnum[b * 128 + c]
                : (c < 256) ? hmean[b * 128 + (c - 128)]
                            : stage[b * 2 + (c - 256)];
        out[OFF_SV + i] = v;
    }
    if (i < M_) out[OFF_MK + i] = 1.0f;
    if (i < B_ * 2) out[OFF_ST + i] = stage[i];
}

// ---------------- launcher ----------------------------------------------------
extern "C" void kernel_launch(void* const* d_in, const int* in_sizes, int n_in,
                              void* d_out, int out_size)
{
    const float* numerical   = (const float*)d_in[0];
    const float* node_feat   = (const float*)d_in[1];
    const float* stage       = (const float*)d_in[2];
    const float* W_num0      = (const float*)d_in[3];
    const float* b_num0      = (const float*)d_in[4];
    const float* W_num1      = (const float*)d_in[5];
    const float* b_num1      = (const float*)d_in[6];
    const float* W_node      = (const float*)d_in[7];
    const float* b_node      = (const float*)d_in[8];
    const float* pos_enc     = (const float*)d_in[9];
    const float* ew1         = (const float*)d_in[10];
    const float* eb1         = (const float*)d_in[11];
    const float* ew2         = (const float*)d_in[12];
    const float* eb2         = (const float*)d_in[13];
    const float* Wg          = (const float*)d_in[14];
    const float* bg          = (const float*)d_in[15];
    const float* Wu          = (const float*)d_in[16];
    const float* bu          = (const float*)d_in[17];
    const float* Wq1         = (const float*)d_in[18];
    const float* bq1         = (const float*)d_in[19];
    const float* Wk1         = (const float*)d_in[20];
    const float* bk1         = (const float*)d_in[21];
    const float* Wv1         = (const float*)d_in[22];
    const float* bv1         = (const float*)d_in[23];
    const float* Win         = (const float*)d_in[24];
    const float* b_in        = (const float*)d_in[25];
    const float* Wout        = (const float*)d_in[26];
    const float* b_out       = (const float*)d_in[27];
    const int*   ei_dis      = (const int*)d_in[28];
    const int*   ei_od       = (const int*)d_in[29];
    const int*   build_idx   = (const int*)d_in[31];
    float* out = (float*)d_out;

    float *p_h, *p_t, *p_fhb, *p_accb, *p_degb, *p_hb;
    float *p_q2, *p_k2, *p_v2, *p_oh, *p_hnum, *p_hmean, *p_part, *p_Wf, *p_bf, *p_zero;
    __nv_bfloat16* p_Abf;
    cudaGetSymbolAddress((void**)&p_h,    g_h);
    cudaGetSymbolAddress((void**)&p_t,    g_t);
    cudaGetSymbolAddress((void**)&p_fhb,  g_fhb);
    cudaGetSymbolAddress((void**)&p_accb, g_accb);
    cudaGetSymbolAddress((void**)&p_degb, g_degb);
    cudaGetSymbolAddress((void**)&p_hb,   g_hb);
    cudaGetSymbolAddress((void**)&p_q2,   g_q2);
    cudaGetSymbolAddress((void**)&p_k2,   g_k2);
    cudaGetSymbolAddress((void**)&p_v2,   g_v2);
    cudaGetSymbolAddress((void**)&p_oh,   g_oh);
    cudaGetSymbolAddress((void**)&p_hnum, g_hnum);
    cudaGetSymbolAddress((void**)&p_hmean,g_hmean);
    cudaGetSymbolAddress((void**)&p_part, g_part);
    cudaGetSymbolAddress((void**)&p_Wf,   g_Wf);
    cudaGetSymbolAddress((void**)&p_bf,   g_bf);
    cudaGetSymbolAddress((void**)&p_zero, g_zero);
    cudaGetSymbolAddress((void**)&p_Abf,  g_Abf);

    // fused attention projection weights: Wf = W{q,k,v}1[256,128] @ Win-slice (K=128)
    gemm_k<<<2, 256>>>(Wq1, 128, Win, 384, 0,   p_zero, 0, p_Wf,         128, 0, nullptr);
    gemm_k<<<2, 256>>>(Wk1, 128, Win, 384, 128, p_zero, 0, p_Wf + 32768, 128, 0, nullptr);
    gemm_k<<<2, 256>>>(Wv1, 128, Win, 384, 256, p_zero, 0, p_Wf + 65536, 128, 0, nullptr);
    fused_bias_k<<<3, 128>>>(bq1, bk1, bv1, Win, b_in, p_bf);

    hnum_k<<<1, 256>>>(numerical, W_num0, b_num0, W_num1, b_num1, p_hnum);

    // h = tanh(node_feature @ W_node + b_node) + pos_enc (fp32 root)
    gemm_k<<<256, 256>>>(node_feat, 32, W_node, 128, 0, b_node, 0, p_h, 32, 2, pos_enc);

    // zero adjacency (bf16, both branches: 134MB = 33.5M floats) + degrees
    zero_k<<<(int)((2L*B_*N_*N_/2)/1024), 256>>>((float*)p_Abf, 2L*B_*N_*N_/2);
    zero_k<<<(2*M_)/1024, 256>>>(p_degb, 2*M_);

    // edge MLPs for both branches (weights differ -> 4 launches, shared t buffer)
    tgemm_k<<<256, 256>>>(p_h, 128, nullptr, nullptr, nullptr, 0,
                          ew1 + 32768, 128, 0, eb1, 256, p_t, 128, 128, 1);
    tgemm_k<<<256, 256>>>(p_t, 128, nullptr, nullptr, nullptr, 0,
                          ew1 + 49152, 128, 0, eb1, 384, p_fhb, 128, 128, 1);
    tgemm_k<<<256, 256>>>(p_h, 128, nullptr, nullptr, nullptr, 0,
                          ew2 + 32768, 128, 0, eb2, 256, p_t, 128, 128, 1);
    tgemm_k<<<256, 256>>>(p_t, 128, nullptr, nullptr, nullptr, 0,
                          ew2 + 49152, 128, 0, eb2, 384, p_fhb + M_*D_, 128, 128, 1);

    // build adjacency counts (both branches) and aggregate via batched GEMM
    edgebuild2_k<<<2*B_*E_/256, 256>>>(ei_dis, ei_od, p_Abf, p_degb);
    adj_tgemm_k<<<dim3(8, 32, 2), 256>>>(p_Abf, p_fhb, p_accb);

    // fused gate+update+combine for both branches -> hb[0], hb[1]
    gu_k<<<dim3(M_/64, 2), 256>>>(p_h, p_accb, p_degb, Wg, bg, Wu, bu, p_hb);

    // q2 / k2 / v2 projections (all tensor-core); A = [hb0 | hb1]
    tgemm_k<<<256, 256>>>(p_hb, 128, p_hb + M_*D_, nullptr, nullptr, 0,
                          p_Wf, 128, 0, p_bf, 0, p_q2, 128, 256, 0);
    tgemm_k<<<64, 256>>>(p_hb, 128, p_hb + M_*D_, nullptr, build_idx, 256,
                         p_Wf + 32768, 128, 0, p_bf, 128, p_k2, 128, 256, 0);
    tgemm_k<<<64, 256>>>(p_hb, 128, p_hb + M_*D_, nullptr, build_idx, 256,
                         p_Wf + 65536, 128, 0, p_bf, 256, p_v2, 128, 256, 0);

    // attention
    attn2_k<<<dim3(4, H_, B_), 256>>>(p_q2, p_k2, p_v2, p_oh);

    // h_att = oh @ W_out + b_out
    tgemm_k<<<256, 256>>>(p_oh, 128, nullptr, nullptr, nullptr, 0,
                          Wout, 128, 0, b_out, 0, out, 128, 128, 0);

    // mean + tail
    mean1_k<<<dim3(32, 8), 128>>>(out, p_part);
    mean2_k<<<32, 128>>>(p_part, p_hmean);
    tail_k<<<129, 256>>>(p_hnum, p_hmean, stage, out);

    (void)in_sizes; (void)n_in; (void)out_size;
}

// round 10
// speedup vs baseline: 2.5604x; 1.2071x over previous
#include <cuda_runtime.h>
#include <cuda_bf16.h>
#include <math.h>
#include <stdint.h>

// Problem constants
#define B_   32
#define N_   1024
#define E_   16384
#define D_   128
#define M_   (B_*N_)      // 32768
#define KB_  256
#define H_   8
#define HD_  16
#define EPSF 1e-6f

#define OFF_SV (M_*D_)
#define OFF_MK (OFF_SV + B_*258)
#define OFF_ST (OFF_MK + M_)

// ---------------- scratch ----------------
__device__ float g_h   [M_*D_];
__device__ float g_t   [M_*D_];
__device__ float g_fhb [2*M_*D_];
__device__ float g_accb[2*M_*D_];   // pre-scaled by 1/(deg+eps)
__device__ float g_degb[2*M_];
__device__ float g_hb  [2*M_*D_];
__device__ float g_q2  [M_*D_];
__device__ float g_k2  [B_*KB_*D_];
__device__ float g_v2  [B_*KB_*D_];
__device__ float g_oh  [M_*D_];
__device__ float g_hnum [B_*128];
__device__ float g_hmean[B_*128];
__device__ float g_part [B_*8*128];
__device__ float g_Wf  [3*256*128];
__device__ float g_bf  [3*128];
__device__ __nv_bfloat16 g_Abf[2L*B_*N_*N_];   // adjacency counts (134MB)

// ---------------- helpers ----------------
__device__ __forceinline__ void mma_tf32(float c[4], const uint32_t a[4], const uint32_t b[2]) {
    asm volatile(
        "mma.sync.aligned.m16n8k8.row.col.f32.tf32.tf32.f32 "
        "{%0,%1,%2,%3}, {%4,%5,%6,%7}, {%8,%9}, {%0,%1,%2,%3};"
        : "+f"(c[0]), "+f"(c[1]), "+f"(c[2]), "+f"(c[3])
        : "r"(a[0]), "r"(a[1]), "r"(a[2]), "r"(a[3]), "r"(b[0]), "r"(b[1]));
}

__device__ __forceinline__ void cp16(uint32_t dst, const void* src) {
    asm volatile("cp.async.ca.shared.global [%0], [%1], 16;" :: "r"(dst), "l"(src));
}
__device__ __forceinline__ uint32_t s2u(const void* p) {
    return (uint32_t)__cvta_generic_to_shared(p);
}
#define CP_COMMIT() asm volatile("cp.async.commit_group;")
#define CP_WAIT(n)  asm volatile("cp.async.wait_group %0;" :: "n"(n))

// fast exp on FMA pipe: exp(x) = 2^n * P(f), P(f)~=2^f, f in [-0.5,0.5]
__device__ __forceinline__ float fexp(float x) {
    x = fmaxf(x, -87.0f);
    float t = x * 1.4426950408889634f;
    float fn = rintf(t);
    float f = t - fn;
    float p = 1.3333558146e-3f;
    p = fmaf(p, f, 9.6179662376e-3f);
    p = fmaf(p, f, 5.5490420128e-2f);
    p = fmaf(p, f, 2.4022650696e-1f);
    p = fmaf(p, f, 6.9314718056e-1f);
    p = fmaf(p, f, 1.0f);
    int n = (int)fn;
    float sc = __int_as_float((n + 127) << 23);
    return p * sc;
}

// ------- tf32 GEMM w/ cp.async double-buffer: C = epi(A@W + bias) ------------
// A virtual concat [A1(lda1) | A2(128)]. Optional rowmap gather. epi: 0 none, 1 tanh.
__global__ void __launch_bounds__(256, 2) tgemm_k(
    const float* __restrict__ A1, int lda1,
    const float* __restrict__ A2,
    const int*   __restrict__ rowmap, int mapMod,
    const float* __restrict__ W, int ldw, int wOff,
    const float* __restrict__ bias, int bOff,
    float* __restrict__ C,
    int K1, int K, int epi)
{
    __shared__ float As[2][128][20];
    __shared__ float Bs[2][16][136];
    const int tid = threadIdx.x;
    const int m0  = blockIdx.x * 128;
    const int warp = tid >> 5, lane = tid & 31;
    const int m0w = (warp >> 2) * 64, n0w = (warp & 3) * 32;
    const int g = lane >> 2, tig = lane & 3;

    // A loader: row = tid>>1, two 16B chunks at cols ac8, ac8+4
    const int arow = tid >> 1, ac8 = (tid & 1) * 8;
    int apr;
    { int gm = m0 + arow; apr = rowmap ? (gm / mapMod) * N_ + rowmap[gm % mapMod] : gm; }
    // B loader: row = tid>>4, two chunks at bc8, bc8+4
    const int brow = tid >> 4, bc8 = (tid & 15) * 8;

    float c[4][4][4];
    #pragma unroll
    for (int mf = 0; mf < 4; mf++)
        #pragma unroll
        for (int nf = 0; nf < 4; nf++)
            #pragma unroll
            for (int q = 0; q < 4; q++) c[mf][nf][q] = 0.f;

    // prologue
    {
        #pragma unroll
        for (int j = 0; j < 2; j++) {
            int k = ac8 + j * 4;
            const float* src = (k < K1) ? &A1[(long)apr * lda1 + k]
                                        : &A2[(long)apr * 128 + (k - K1)];
            cp16(s2u(&As[0][arow][ac8 + j * 4]), src);
        }
        #pragma unroll
        for (int j = 0; j < 2; j++)
            cp16(s2u(&Bs[0][brow][bc8 + j * 4]), &W[(long)brow * ldw + wOff + bc8 + j * 4]);
        CP_COMMIT();
    }

    int buf = 0;
    for (int k0 = 0; k0 < K; k0 += 16) {
        bool nxt = (k0 + 16) < K;
        if (nxt) {
            int kn = k0 + 16;
            #pragma unroll
            for (int j = 0; j < 2; j++) {
                int k = kn + ac8 + j * 4;
                const float* src = (k < K1) ? &A1[(long)apr * lda1 + k]
                                            : &A2[(long)apr * 128 + (k - K1)];
                cp16(s2u(&As[buf ^ 1][arow][ac8 + j * 4]), src);
            }
            #pragma unroll
            for (int j = 0; j < 2; j++)
                cp16(s2u(&Bs[buf ^ 1][brow][bc8 + j * 4]),
                     &W[(long)(kn + brow) * ldw + wOff + bc8 + j * 4]);
            CP_COMMIT();
            CP_WAIT(1);
        } else {
            CP_WAIT(0);
        }
        __syncthreads();
        #pragma unroll
        for (int kk = 0; kk < 2; kk++) {
            int kb = kk * 8;
            uint32_t b[4][2];
            #pragma unroll
            for (int nf = 0; nf < 4; nf++) {
                int nc = n0w + nf * 8 + g;
                b[nf][0] = __float_as_uint(Bs[buf][kb + tig    ][nc]);
                b[nf][1] = __float_as_uint(Bs[buf][kb + tig + 4][nc]);
            }
            #pragma unroll
            for (int mf = 0; mf < 4; mf++) {
                int mcol = m0w + mf * 16 + g;
                uint32_t a[4];
                a[0] = __float_as_uint(As[buf][mcol    ][kb + tig]);
                a[1] = __float_as_uint(As[buf][mcol + 8][kb + tig]);
                a[2] = __float_as_uint(As[buf][mcol    ][kb + tig + 4]);
                a[3] = __float_as_uint(As[buf][mcol + 8][kb + tig + 4]);
                #pragma unroll
                for (int nf = 0; nf < 4; nf++)
                    mma_tf32(c[mf][nf], a, b[nf]);
            }
        }
        __syncthreads();
        buf ^= 1;
    }
    #pragma unroll
    for (int mf = 0; mf < 4; mf++) {
        int row0 = m0 + m0w + mf * 16 + g;
        #pragma unroll
        for (int nf = 0; nf < 4; nf++) {
            int col = n0w + nf * 8 + 2 * tig;
            float b0 = bias[bOff + col], b1 = bias[bOff + col + 1];
            float v00 = c[mf][nf][0] + b0, v01 = c[mf][nf][1] + b1;
            float v10 = c[mf][nf][2] + b0, v11 = c[mf][nf][3] + b1;
            if (epi >= 1) { v00 = tanhf(v00); v01 = tanhf(v01); v10 = tanhf(v10); v11 = tanhf(v11); }
            *(float2*)&C[(long)row0 * 128 + col]       = make_float2(v00, v01);
            *(float2*)&C[(long)(row0 + 8) * 128 + col] = make_float2(v10, v11);
        }
    }
}

// ---- adjacency aggregation, bf16 A, double-buffered; epilogue scales by deg -
__global__ void __launch_bounds__(256, 2) adj_tgemm_k(
    const __nv_bfloat16* __restrict__ Abf,
    const float* __restrict__ fhb,
    const float* __restrict__ degb,
    float* __restrict__ accb)
{
    __shared__ float As[2][128][20];
    __shared__ float Bs[2][16][136];
    const int tid = threadIdx.x;
    const int bb = blockIdx.y, br = blockIdx.z;
    const int m0 = blockIdx.x * 128;
    const int warp = tid >> 5, lane = tid & 31;
    const int m0w = (warp >> 2) * 64, n0w = (warp & 3) * 32;
    const int g = lane >> 2, tig = lane & 3;
    const __nv_bfloat16* Ab = Abf + (long)br * B_ * N_ * N_ + (long)bb * N_ * N_;
    const float* fhp = fhb + (long)br * M_ * D_ + (long)bb * N_ * D_;
    const float* deg = degb + br * M_;
    float* accp = accb + (long)br * M_ * D_;

    const int arow = tid >> 1, ac8 = (tid & 1) * 8;   // 8 bf16 = 16B
    const int brow = tid >> 4, bc8 = (tid & 15) * 8;

    float c[4][4][4];
    #pragma unroll
    for (int mf = 0; mf < 4; mf++)
        #pragma unroll
        for (int nf = 0; nf < 4; nf++)
            #pragma unroll
            for (int q = 0; q < 4; q++) c[mf][nf][q] = 0.f;

    auto cvt_store = [&](int buf, uint4 raw) {
        const __nv_bfloat162* p2 = (const __nv_bfloat162*)&raw;
        #pragma unroll
        for (int j = 0; j < 4; j++) {
            float2 f = __bfloat1622float2(p2[j]);
            As[buf][arow][ac8 + 2 * j]     = f.x;
            As[buf][arow][ac8 + 2 * j + 1] = f.y;
        }
    };

    // prologue: A regs k0=0, B cp k0=0 -> buf0
    uint4 r0 = *(const uint4*)(Ab + (long)(m0 + arow) * N_ + ac8);
    #pragma unroll
    for (int j = 0; j < 2; j++)
        cp16(s2u(&Bs[0][brow][bc8 + j * 4]), &fhp[(long)brow * D_ + bc8 + j * 4]);
    CP_COMMIT();
    cvt_store(0, r0);

    int buf = 0;
    for (int k0 = 0; k0 < N_; k0 += 16) {
        bool nxt = (k0 + 16) < N_;
        uint4 r2;
        if (nxt) {
            int kn = k0 + 16;
            r2 = *(const uint4*)(Ab + (long)(m0 + arow) * N_ + kn + ac8);
            #pragma unroll
            for (int j = 0; j < 2; j++)
                cp16(s2u(&Bs[buf ^ 1][brow][bc8 + j * 4]),
                     &fhp[(long)(kn + brow) * D_ + bc8 + j * 4]);
            CP_COMMIT();
            CP_WAIT(1);
        } else {
            CP_WAIT(0);
        }
        __syncthreads();
        #pragma unroll
        for (int kk = 0; kk < 2; kk++) {
            int kb = kk * 8;
            uint32_t b[4][2];
            #pragma unroll
            for (int nf = 0; nf < 4; nf++) {
                int nc = n0w + nf * 8 + g;
                b[nf][0] = __float_as_uint(Bs[buf][kb + tig    ][nc]);
                b[nf][1] = __float_as_uint(Bs[buf][kb + tig + 4][nc]);
            }
            #pragma unroll
            for (int mf = 0; mf < 4; mf++) {
                int mcol = m0w + mf * 16 + g;
                uint32_t a[4];
                a[0] = __float_as_uint(As[buf][mcol    ][kb + tig]);
                a[1] = __float_as_uint(As[buf][mcol + 8][kb + tig]);
                a[2] = __float_as_uint(As[buf][mcol    ][kb + tig + 4]);
                a[3] = __float_as_uint(As[buf][mcol + 8][kb + tig + 4]);
                #pragma unroll
                for (int nf = 0; nf < 4; nf++)
                    mma_tf32(c[mf][nf], a, b[nf]);
            }
        }
        if (nxt) cvt_store(buf ^ 1, r2);
        __syncthreads();
        buf ^= 1;
    }
    #pragma unroll
    for (int mf = 0; mf < 4; mf++) {
        int rowl = m0 + m0w + mf * 16 + g;
        int row0 = bb * N_ + rowl;
        float s0 = 1.0f / (deg[row0] + EPSF);
        float s1 = 1.0f / (deg[row0 + 8] + EPSF);
        #pragma unroll
        for (int nf = 0; nf < 4; nf++) {
            int col = n0w + nf * 8 + 2 * tig;
            *(float2*)&accp[(long)row0 * 128 + col] =
                make_float2(c[mf][nf][0] * s0, c[mf][nf][1] * s0);
            *(float2*)&accp[(long)(row0 + 8) * 128 + col] =
                make_float2(c[mf][nf][2] * s1, c[mf][nf][3] * s1);
        }
    }
}

// ---- fused gate+update+combine dual GEMM (cp.async double-buffered) ---------
// A = [h | acc_scaled] (K=256), hout = tanh(A@Wg+bg)*tanh(A@Wu+bu)+(1-g)*h
__global__ void __launch_bounds__(256, 2) gu_k(
    const float* __restrict__ h,
    const float* __restrict__ accb,
    const float* __restrict__ Wg, const float* __restrict__ bg,
    const float* __restrict__ Wu, const float* __restrict__ bu,
    float* __restrict__ houtb)
{
    const int br = blockIdx.y;
    const float* acc = accb + (long)br * M_ * D_;
    float* hout = houtb + (long)br * M_ * D_;

    __shared__ float As [2][64][20];
    __shared__ float BsG[2][16][136];
    __shared__ float BsU[2][16][136];
    const int tid = threadIdx.x;
    const int m0 = blockIdx.x * 64;
    const int warp = tid >> 5, lane = tid & 31;
    const int m0w = (warp >> 2) * 32, n0w = (warp & 3) * 32;
    const int g = lane >> 2, tig = lane & 3;

    const int arow = tid >> 2, ac4 = (tid & 3) * 4;   // 1 chunk/thread
    const int brow = tid >> 4, bc8 = (tid & 15) * 8;  // 2 chunks per B matrix

    float cg[2][4][4], cu[2][4][4];
    #pragma unroll
    for (int mf = 0; mf < 2; mf++)
        #pragma unroll
        for (int nf = 0; nf < 4; nf++)
            #pragma unroll
            for (int q = 0; q < 4; q++) { cg[mf][nf][q] = 0.f; cu[mf][nf][q] = 0.f; }

    auto issue = [&](int k0, int buf) {
        int k = k0 + ac4;
        const float* src = (k < 128) ? &h[(long)(m0 + arow) * 128 + k]
                                     : &acc[(long)(m0 + arow) * 128 + (k - 128)];
        cp16(s2u(&As[buf][arow][ac4]), src);
        #pragma unroll
        for (int j = 0; j < 2; j++) {
            cp16(s2u(&BsG[buf][brow][bc8 + j * 4]), &Wg[(long)(k0 + brow) * 128 + bc8 + j * 4]);
            cp16(s2u(&BsU[buf][brow][bc8 + j * 4]), &Wu[(long)(k0 + brow) * 128 + bc8 + j * 4]);
        }
        CP_COMMIT();
    };

    issue(0, 0);
    int buf = 0;
    for (int k0 = 0; k0 < 256; k0 += 16) {
        bool nxt = (k0 + 16) < 256;
        if (nxt) { issue(k0 + 16, buf ^ 1); CP_WAIT(1); }
        else     { CP_WAIT(0); }
        __syncthreads();
        #pragma unroll
        for (int kk = 0; kk < 2; kk++) {
            int kb = kk * 8;
            uint32_t bgf[4][2], buf2[4][2];
            #pragma unroll
            for (int nf = 0; nf < 4; nf++) {
                int nc = n0w + nf * 8 + g;
                bgf[nf][0]  = __float_as_uint(BsG[buf][kb + tig    ][nc]);
                bgf[nf][1]  = __float_as_uint(BsG[buf][kb + tig + 4][nc]);
                buf2[nf][0] = __float_as_uint(BsU[buf][kb + tig    ][nc]);
                buf2[nf][1] = __float_as_uint(BsU[buf][kb + tig + 4][nc]);
            }
            #pragma unroll
            for (int mf = 0; mf < 2; mf++) {
                int mcol = m0w + mf * 16 + g;
                uint32_t a[4];
                a[0] = __float_as_uint(As[buf][mcol    ][kb + tig]);
                a[1] = __float_as_uint(As[buf][mcol + 8][kb + tig]);
                a[2] = __float_as_uint(As[buf][mcol    ][kb + tig + 4]);
                a[3] = __float_as_uint(As[buf][mcol + 8][kb + tig + 4]);
                #pragma unroll
                for (int nf = 0; nf < 4; nf++) {
                    mma_tf32(cg[mf][nf], a, bgf[nf]);
                    mma_tf32(cu[mf][nf], a, buf2[nf]);
                }
            }
        }
        __syncthreads();
        buf ^= 1;
    }
    #pragma unroll
    for (int mf = 0; mf < 2; mf++) {
        int row0 = m0 + m0w + mf * 16 + g;
        #pragma unroll
        for (int nf = 0; nf < 4; nf++) {
            int col = n0w + nf * 8 + 2 * tig;
            float bg0 = bg[col], bg1 = bg[col + 1];
            float bu0 = bu[col], bu1 = bu[col + 1];
            float2 h0 = *(const float2*)&h[(long)row0 * 128 + col];
            float2 h1 = *(const float2*)&h[(long)(row0 + 8) * 128 + col];
            float G00 = tanhf(cg[mf][nf][0] + bg0), G01 = tanhf(cg[mf][nf][1] + bg1);
            float G10 = tanhf(cg[mf][nf][2] + bg0), G11 = tanhf(cg[mf][nf][3] + bg1);
            float U00 = tanhf(cu[mf][nf][0] + bu0), U01 = tanhf(cu[mf][nf][1] + bu1);
            float U10 = tanhf(cu[mf][nf][2] + bu0), U11 = tanhf(cu[mf][nf][3] + bu1);
            *(float2*)&hout[(long)row0 * 128 + col] =
                make_float2(G00 * U00 + (1.f - G00) * h0.x, G01 * U01 + (1.f - G01) * h0.y);
            *(float2*)&hout[(long)(row0 + 8) * 128 + col] =
                make_float2(G10 * U10 + (1.f - G10) * h1.x, G11 * U11 + (1.f - G11) * h1.y);
        }
    }
}

// ---------------- scalar fp32 GEMM (root layer) ------------------------------
__global__ void __launch_bounds__(256, 2) gemm_k(
    const float* __restrict__ A1, int lda1,
    const float* __restrict__ W, int ldw, int wOff,
    const float* __restrict__ bias,
    float* __restrict__ C,
    int K, int epi, const float* __restrict__ pos)
{
    __shared__ float As[16][128];
    __shared__ float Bs[16][128];
    const int tid = threadIdx.x;
    const int m0  = blockIdx.x * 128;
    const int ty  = tid >> 4, tx = tid & 15;

    float acc[8][8];
    #pragma unroll
    for (int i = 0; i < 8; i++)
        #pragma unroll
        for (int j = 0; j < 8; j++) acc[i][j] = 0.f;

    for (int k0 = 0; k0 < K; k0 += 16) {
        #pragma unroll
        for (int i = 0; i < 2; i++) {
            int idx = tid + i * 256;
            int mr  = idx >> 2, c4 = (idx & 3) * 4;
            float4 v = *(const float4*)&A1[(long)(m0 + mr) * lda1 + k0 + c4];
            As[c4 + 0][mr] = v.x; As[c4 + 1][mr] = v.y;
            As[c4 + 2][mr] = v.z; As[c4 + 3][mr] = v.w;
        }
        #pragma unroll
        for (int i = 0; i < 2; i++) {
            int idx = tid + i * 256;
            int kr  = idx >> 5, c4 = (idx & 31) * 4;
            *(float4*)&Bs[kr][c4] = *(const float4*)&W[(long)(k0 + kr) * ldw + wOff + c4];
        }
        __syncthreads();
        #pragma unroll
        for (int kk = 0; kk < 16; kk++) {
            float a[8], b[8];
            #pragma unroll
            for (int i = 0; i < 8; i++) a[i] = As[kk][ty * 8 + i];
            #pragma unroll
            for (int j = 0; j < 8; j++) b[j] = Bs[kk][tx * 8 + j];
            #pragma unroll
            for (int i = 0; i < 8; i++)
                #pragma unroll
                for (int j = 0; j < 8; j++)
                    acc[i][j] += a[i] * b[j];
        }
        __syncthreads();
    }
    #pragma unroll
    for (int i = 0; i < 8; i++) {
        int gm = m0 + ty * 8 + i;
        #pragma unroll
        for (int j = 0; j < 8; j++) {
            int col = tx * 8 + j;
            float v = acc[i][j] + bias[col];
            if (epi >= 1) v = tanhf(v);
            if (epi == 2) v += pos[(gm % N_) * 128 + col];
            C[(long)gm * 128 + col] = v;
        }
    }
}

// ---- merged preamble: Wf GEMMs (blocks 0-5), fused bias (6), hnum (7) -------
__global__ void __launch_bounds__(256) pre_k(
    const float* __restrict__ Wq1, const float* __restrict__ Wk1,
    const float* __restrict__ Wv1, const float* __restrict__ Win,
    const float* __restrict__ bq1, const float* __restrict__ bk1,
    const float* __restrict__ bv1, const float* __restrict__ b_in,
    const float* __restrict__ num,
    const float* __restrict__ W0, const float* __restrict__ b0,
    const float* __restrict__ W1, const float* __restrict__ b1,
    float* __restrict__ Wf, float* __restrict__ bf, float* __restrict__ hnum)
{
    __shared__ float sm[32 * 256 + 32 * 64];   // 40KB, reused per role
    int tid = threadIdx.x;
    int blk = blockIdx.x;
    if (blk < 6) {
        int which = blk >> 1, tile = blk & 1;
        const float* A = (which == 0) ? Wq1 : (which == 1) ? Wk1 : Wv1;
        int wOff = which * 128;
        float* As = sm;             // [16][128]
        float* Bs = sm + 2048;      // [16][128]
        int m0 = tile * 128;
        int ty = tid >> 4, tx = tid & 15;
        float acc[8][8];
        #pragma unroll
        for (int i = 0; i < 8; i++)
            #pragma unroll
            for (int j = 0; j < 8; j++) acc[i][j] = 0.f;
        for (int k0 = 0; k0 < 128; k0 += 16) {
            #pragma unroll
            for (int i = 0; i < 2; i++) {
                int idx = tid + i * 256;
                int mr = idx >> 2, c4 = (idx & 3) * 4;
                float4 v = *(const float4*)&A[(long)(m0 + mr) * 128 + k0 + c4];
                As[(c4 + 0) * 128 + mr] = v.x; As[(c4 + 1) * 128 + mr] = v.y;
                As[(c4 + 2) * 128 + mr] = v.z; As[(c4 + 3) * 128 + mr] = v.w;
            }
            #pragma unroll
            for (int i = 0; i < 2; i++) {
                int idx = tid + i * 256;
                int kr = idx >> 5, c4 = (idx & 31) * 4;
                *(float4*)&Bs[kr * 128 + c4] = *(const float4*)&Win[(long)(k0 + kr) * 384 + wOff + c4];
            }
            __syncthreads();
            #pragma unroll
            for (int kk = 0; kk < 16; kk++) {
                float a[8], b[8];
                #pragma unroll
                for (int i = 0; i < 8; i++) a[i] = As[kk * 128 + ty * 8 + i];
                #pragma unroll
                for (int j = 0; j < 8; j++) b[j] = Bs[kk * 128 + tx * 8 + j];
                #pragma unroll
                for (int i = 0; i < 8; i++)
                    #pragma unroll
                    for (int j = 0; j < 8; j++)
                        acc[i][j] += a[i] * b[j];
            }
            __syncthreads();
        }
        #pragma unroll
        for (int i = 0; i < 8; i++)
            #pragma unroll
            for (int j = 0; j < 8; j++)
                Wf[which * 32768 + (long)(m0 + ty * 8 + i) * 128 + tx * 8 + j] = acc[i][j];
    } else if (blk == 6) {
        float* sb = sm;
        for (int i = tid; i < 384; i += 256)
            sb[i] = (i < 128) ? bq1[i] : (i < 256) ? bk1[i - 128] : bv1[i - 256];
        __syncthreads();
        for (int col = tid; col < 384; col += 256) {
            float acc = b_in[col];
            int s = col >> 7;
            for (int k = 0; k < 128; k++)
                acc += sb[s * 128 + k] * Win[k * 384 + col];
            bf[col] = acc;
        }
    } else {
        float* sn = sm;             // 32*64
        float* sh = sm + 32 * 64;   // 32*256
        for (int i = tid; i < 32 * 64; i += 256) sn[i] = num[i];
        __syncthreads();
        for (int i = tid; i < 32 * 256; i += 256) {
            int r = i >> 8, c = i & 255;
            float a = b0[c];
            for (int k = 0; k < 64; k++) a += sn[r * 64 + k] * W0[k * 256 + c];
            sh[i] = tanhf(a);
        }
        __syncthreads();
        for (int i = tid; i < 32 * 128; i += 256) {
            int r = i >> 7, c = i & 127;
            float a = b1[c];
            for (int k = 0; k < 256; k++) a += sh[r * 256 + k] * W1[k * 128 + c];
            hnum[i] = tanhf(a);
        }
    }
}

// ---- build adjacency (bf16) + degree, both branches -------------------------
__global__ void __launch_bounds__(256) edgebuild2_k(
    const int* __restrict__ ei0, const int* __restrict__ ei1,
    __nv_bfloat16* __restrict__ Abf, float* __restrict__ degb)
{
    int gidx = blockIdx.x * 256 + threadIdx.x;
    int br = gidx / (B_ * E_);
    int e  = gidx % (B_ * E_);
    const int* ei = br ? ei1 : ei0;
    int b = e / E_;
    long base = (long)br * B_ * N_ * N_ + (long)b * N_ * N_;
    int e0 = ei[2 * e];
    int e1 = ei[2 * e + 1];
    __nv_bfloat16 one = __float2bfloat16(1.0f);
    atomicAdd(&Abf[base + (long)e0 * N_ + e1], one);
    atomicAdd(&Abf[base + (long)e1 * N_ + e0], one);
    atomicAdd(&degb[br * M_ + b * N_ + e0], 1.0f);
    atomicAdd(&degb[br * M_ + b * N_ + e1], 1.0f);
}

__global__ void zero_k(float* __restrict__ p, long n)
{
    long i = ((long)blockIdx.x * 256 + threadIdx.x) * 4;
    if (i < n) *(float4*)&p[i] = make_float4(0.f, 0.f, 0.f, 0.f);
}

// ---------------- attention: 1 row/thread, broadcast K/V, poly exp -----------
__global__ void __launch_bounds__(256) attn2_k(
    const float* __restrict__ q2,
    const float* __restrict__ k2,
    const float* __restrict__ v2,
    float* __restrict__ oh)
{
    __shared__ float Ks[256][16];
    __shared__ float Vs[256][16];
    int qt = blockIdx.x, h = blockIdx.y, b = blockIdx.z;
    int tid = threadIdx.x;

    #pragma unroll
    for (int i = 0; i < 4; i++) {
        int idx = tid + i * 256;
        int j  = idx >> 2;
        int d4 = (idx & 3) * 4;
        *(float4*)&Ks[j][d4] = *(const float4*)&k2[(long)(b * KB_ + j) * D_ + h * HD_ + d4];
        *(float4*)&Vs[j][d4] = *(const float4*)&v2[(long)(b * KB_ + j) * D_ + h * HD_ + d4];
    }
    __syncthreads();

    int qi = qt * 256 + tid;
    const float* qp = &q2[(long)(b * N_ + qi) * D_ + h * HD_];
    float q[16];
    #pragma unroll
    for (int d = 0; d < 16; d += 4) {
        float4 v = *(const float4*)&qp[d];
        q[d] = v.x * 0.25f; q[d+1] = v.y * 0.25f; q[d+2] = v.z * 0.25f; q[d+3] = v.w * 0.25f;
    }

    float m = -1e30f, sum = 0.f;
    float o[16];
    #pragma unroll
    for (int d = 0; d < 16; d++) o[d] = 0.f;

    for (int jj = 0; jj < 256; jj++) {
        float s = 0.f;
        float kreg[16];
        #pragma unroll
        for (int d4 = 0; d4 < 16; d4 += 4) {
            float4 kv = *(const float4*)&Ks[jj][d4];
            kreg[d4] = kv.x; kreg[d4+1] = kv.y; kreg[d4+2] = kv.z; kreg[d4+3] = kv.w;
        }
        #pragma unroll
        for (int d = 0; d < 16; d++) s = fmaf(q[d], kreg[d], s);
        float p;
        if (s > m) {
            float c = fexp(m - s);
            sum *= c;
            #pragma unroll
            for (int d = 0; d < 16; d++) o[d] *= c;
            m = s;
            p = 1.0f;
        } else {
            p = fexp(s - m);
        }
        sum += p;
        #pragma unroll
        for (int d4 = 0; d4 < 16; d4 += 4) {
            float4 vv = *(const float4*)&Vs[jj][d4];
            o[d4]   = fmaf(p, vv.x, o[d4]);
            o[d4+1] = fmaf(p, vv.y, o[d4+1]);
            o[d4+2] = fmaf(p, vv.z, o[d4+2]);
            o[d4+3] = fmaf(p, vv.w, o[d4+3]);
        }
    }
    float inv = 1.0f / sum;
    float* op = &oh[(long)(b * N_ + qi) * D_ + h * HD_];
    #pragma unroll
    for (int d = 0; d < 16; d += 4)
        *(float4*)&op[d] = make_float4(o[d]*inv, o[d+1]*inv, o[d+2]*inv, o[d+3]*inv);
}

// ---------------- mean + tail -------------------------------------------------
__global__ void mean1_k(const float* __restrict__ att, float* __restrict__ part)
{
    int b = blockIdx.x, ch = blockIdx.y, c = threadIdx.x;
    float s = 0.f;
    int n0 = ch * 128;
    for (int n = n0; n < n0 + 128; n++)
        s += att[(long)(b * N_ + n) * D_ + c];
    part[(b * 8 + ch) * 128 + c] = s;
}

__global__ void mean2_k(const float* __restrict__ part, float* __restrict__ hmean)
{
    int b = blockIdx.x, c = threadIdx.x;
    float s = 0.f;
    #pragma unroll
    for (int ch = 0; ch < 8; ch++)
        s += part[(b * 8 + ch) * 128 + c];
    hmean[b * 128 + c] = s * (1.0f / N_);
}

__global__ void tail_k(const float* __restrict__ hnum,
                       const float* __restrict__ hmean,
                       const float* __restrict__ stage,
                       float* __restrict__ out)
{
    int i = blockIdx.x * 256 + threadIdx.x;
    if (i < B_ * 258) {
        int b = i / 258, c = i % 258;
        float v = (c < 128) ? hnum[b * 128 + c]
                : (c < 256) ? hmean[b * 128 + (c - 128)]
                            : stage[b * 2 + (c - 256)];
        out[OFF_SV + i] = v;
    }
    if (i < M_) out[OFF_MK + i] = 1.0f;
    if (i < B_ * 2) out[OFF_ST + i] = stage[i];
}

// ---------------- launcher ----------------------------------------------------
extern "C" void kernel_launch(void* const* d_in, const int* in_sizes, int n_in,
                              void* d_out, int out_size)
{
    const float* numerical   = (const float*)d_in[0];
    const float* node_feat   = (const float*)d_in[1];
    const float* stage       = (const float*)d_in[2];
    const float* W_num0      = (const float*)d_in[3];
    const float* b_num0      = (const float*)d_in[4];
    const float* W_num1      = (const float*)d_in[5];
    const float* b_num1      = (const float*)d_in[6];
    const float* W_node      = (const float*)d_in[7];
    const float* b_node      = (const float*)d_in[8];
    const float* pos_enc     = (const float*)d_in[9];
    const float* ew1         = (const float*)d_in[10];
    const float* eb1         = (const float*)d_in[11];
    const float* ew2         = (const float*)d_in[12];
    const float* eb2         = (const float*)d_in[13];
    const float* Wg          = (const float*)d_in[14];
    const float* bg          = (const float*)d_in[15];
    const float* Wu          = (const float*)d_in[16];
    const float* bu          = (const float*)d_in[17];
    const float* Wq1         = (const float*)d_in[18];
    const float* bq1         = (const float*)d_in[19];
    const float* Wk1         = (const float*)d_in[20];
    const float* bk1         = (const float*)d_in[21];
    const float* Wv1         = (const float*)d_in[22];
    const float* bv1         = (const float*)d_in[23];
    const float* Win         = (const float*)d_in[24];
    const float* b_in        = (const float*)d_in[25];
    const float* Wout        = (const float*)d_in[26];
    const float* b_out       = (const float*)d_in[27];
    const int*   ei_dis      = (const int*)d_in[28];
    const int*   ei_od       = (const int*)d_in[29];
    const int*   build_idx   = (const int*)d_in[31];
    float* out = (float*)d_out;

    float *p_h, *p_t, *p_fhb, *p_accb, *p_degb, *p_hb;
    float *p_q2, *p_k2, *p_v2, *p_oh, *p_hnum, *p_hmean, *p_part, *p_Wf, *p_bf;
    __nv_bfloat16* p_Abf;
    cudaGetSymbolAddress((void**)&p_h,    g_h);
    cudaGetSymbolAddress((void**)&p_t,    g_t);
    cudaGetSymbolAddress((void**)&p_fhb,  g_fhb);
    cudaGetSymbolAddress((void**)&p_accb, g_accb);
    cudaGetSymbolAddress((void**)&p_degb, g_degb);
    cudaGetSymbolAddress((void**)&p_hb,   g_hb);
    cudaGetSymbolAddress((void**)&p_q2,   g_q2);
    cudaGetSymbolAddress((void**)&p_k2,   g_k2);
    cudaGetSymbolAddress((void**)&p_v2,   g_v2);
    cudaGetSymbolAddress((void**)&p_oh,   g_oh);
    cudaGetSymbolAddress((void**)&p_hnum, g_hnum);
    cudaGetSymbolAddress((void**)&p_hmean,g_hmean);
    cudaGetSymbolAddress((void**)&p_part, g_part);
    cudaGetSymbolAddress((void**)&p_Wf,   g_Wf);
    cudaGetSymbolAddress((void**)&p_bf,   g_bf);
    cudaGetSymbolAddress((void**)&p_Abf,  g_Abf);

    // merged preamble: Wf GEMMs + fused bias + h_num MLP
    pre_k<<<8, 256>>>(Wq1, Wk1, Wv1, Win, bq1, bk1, bv1, b_in,
                      numerical, W_num0, b_num0, W_num1, b_num1,
                      p_Wf, p_bf, p_hnum);

    // h = tanh(node_feature @ W_node + b_node) + pos_enc (fp32 root)
    gemm_k<<<256, 256>>>(node_feat, 32, W_node, 128, 0, b_node, p_h, 32, 2, pos_enc);

    // zero adjacency (bf16 both branches) + degrees
    zero_k<<<(int)((2L*B_*N_*N_/2)/1024), 256>>>((float*)p_Abf, 2L*B_*N_*N_/2);
    zero_k<<<(2*M_)/1024, 256>>>(p_degb, 2*M_);

    // edge MLPs for both branches
    tgemm_k<<<256, 256>>>(p_h, 128, nullptr, nullptr, 0,
                          ew1 + 32768, 128, 0, eb1, 256, p_t, 128, 128, 1);
    tgemm_k<<<256, 256>>>(p_t, 128, nullptr, nullptr, 0,
                          ew1 + 49152, 128, 0, eb1, 384, p_fhb, 128, 128, 1);
    tgemm_k<<<256, 256>>>(p_h, 128, nullptr, nullptr, 0,
                          ew2 + 32768, 128, 0, eb2, 256, p_t, 128, 128, 1);
    tgemm_k<<<256, 256>>>(p_t, 128, nullptr, nullptr, 0,
                          ew2 + 49152, 128, 0, eb2, 384, p_fhb + M_*D_, 128, 128, 1);

    // build + aggregate (acc pre-scaled by 1/(deg+eps) in adj epilogue)
    edgebuild2_k<<<2*B_*E_/256, 256>>>(ei_dis, ei_od, p_Abf, p_degb);
    adj_tgemm_k<<<dim3(8, 32, 2), 256>>>(p_Abf, p_fhb, p_degb, p_accb);

    // fused gate+update+combine
    gu_k<<<dim3(M_/64, 2), 256>>>(p_h, p_accb, Wg, bg, Wu, bu, p_hb);

    // q2 / k2 / v2 projections
    tgemm_k<<<256, 256>>>(p_hb, 128, p_hb + M_*D_, nullptr, 0,
                          p_Wf, 128, 0, p_bf, 0, p_q2, 128, 256, 0);
    tgemm_k<<<64, 256>>>(p_hb, 128, p_hb + M_*D_, build_idx, 256,
                         p_Wf + 32768, 128, 0, p_bf, 128, p_k2, 128, 256, 0);
    tgemm_k<<<64, 256>>>(p_hb, 128, p_hb + M_*D_, build_idx, 256,
                         p_Wf + 65536, 128, 0, p_bf, 256, p_v2, 128, 256, 0);

    // attention
    attn2_k<<<dim3(4, H_, B_), 256>>>(p_q2, p_k2, p_v2, p_oh);

    // h_att = oh @ W_out + b_out
    tgemm_k<<<256, 256>>>(p_oh, 128, nullptr, nullptr, 0,
                          Wout, 128, 0, b_out, 0, out, 128, 128, 0);

    // mean + tail
    mean1_k<<<dim3(32, 8), 128>>>(out, p_part);
    mean2_k<<<32, 128>>>(p_part, p_hmean);
    tail_k<<<129, 256>>>(p_hnum, p_hmean, stage, out);

    (void)in_sizes; (void)n_in; (void)out_size;
}